// round 1
// baseline (speedup 1.0000x reference)
#include <cuda_runtime.h>
#include <math.h>

#define D_MODEL 2048
#define S_LEN   2048
#define BATCH   2
#define NROWS   (BATCH * S_LEN)   // 4096
#define N_HEADS 16
#define D_HEAD  128

// ---------------- scratch (alloc-free rule: __device__ globals) ----------------
__device__ float g_Xn[(size_t)NROWS * D_MODEL];
__device__ float g_Q [(size_t)NROWS * D_MODEL];
__device__ float g_K [(size_t)NROWS * D_MODEL];
__device__ float g_V [(size_t)NROWS * D_MODEL];
__device__ float g_AV[(size_t)NROWS * D_MODEL];

// ---------------- LayerNorm: one block per row ----------------
__global__ __launch_bounds__(256) void ln_kernel(
    const float* __restrict__ X, const float* __restrict__ gam,
    const float* __restrict__ bet, float* __restrict__ Xn)
{
    int row = blockIdx.x;
    const float4* x4 = (const float4*)(X + (size_t)row * D_MODEL);
    float4*       o4 = (float4*)(Xn + (size_t)row * D_MODEL);
    const float4* g4 = (const float4*)gam;
    const float4* b4 = (const float4*)bet;
    int tid = threadIdx.x;

    float4 v0 = x4[tid];
    float4 v1 = x4[tid + 256];
    float s  = v0.x + v0.y + v0.z + v0.w + v1.x + v1.y + v1.z + v1.w;
    float ss = v0.x*v0.x + v0.y*v0.y + v0.z*v0.z + v0.w*v0.w
             + v1.x*v1.x + v1.y*v1.y + v1.z*v1.z + v1.w*v1.w;

    #pragma unroll
    for (int off = 16; off; off >>= 1) {
        s  += __shfl_xor_sync(0xffffffffu, s,  off);
        ss += __shfl_xor_sync(0xffffffffu, ss, off);
    }
    __shared__ float rs[8], rss[8];
    __shared__ float s_mean, s_rstd;
    int w = tid >> 5, l = tid & 31;
    if (l == 0) { rs[w] = s; rss[w] = ss; }
    __syncthreads();
    if (tid == 0) {
        float t = 0.f, tt = 0.f;
        #pragma unroll
        for (int i = 0; i < 8; i++) { t += rs[i]; tt += rss[i]; }
        float mean = t * (1.f / D_MODEL);
        float var  = tt * (1.f / D_MODEL) - mean * mean;
        s_mean = mean;
        s_rstd = rsqrtf(var + 1e-5f);
    }
    __syncthreads();
    float mean = s_mean, rstd = s_rstd;

    float4 g0 = g4[tid], g1 = g4[tid + 256];
    float4 c0 = b4[tid], c1 = b4[tid + 256];
    float4 r0, r1;
    r0.x = (v0.x - mean) * rstd * g0.x + c0.x;
    r0.y = (v0.y - mean) * rstd * g0.y + c0.y;
    r0.z = (v0.z - mean) * rstd * g0.z + c0.z;
    r0.w = (v0.w - mean) * rstd * g0.w + c0.w;
    r1.x = (v1.x - mean) * rstd * g1.x + c1.x;
    r1.y = (v1.y - mean) * rstd * g1.y + c1.y;
    r1.z = (v1.z - mean) * rstd * g1.z + c1.z;
    r1.w = (v1.w - mean) * rstd * g1.w + c1.w;
    o4[tid]       = r0;
    o4[tid + 256] = r1;
}

// ---------------- SGEMM: C[M,N] = A[M,K] @ W[K,N] + bias, M=4096, N=K=2048 ----------------
// 128x128 block, BK=8, 256 threads, 8x8 per thread.
__global__ __launch_bounds__(256) void sgemm_bias(
    const float* __restrict__ A, const float* __restrict__ W,
    const float* __restrict__ bias, float* __restrict__ C)
{
    const int Kdim = D_MODEL, Ndim = D_MODEL;
    __shared__ float As[8][128];
    __shared__ float Bs[8][128];

    int tid  = threadIdx.x;
    int bx   = blockIdx.x * 128;
    int by   = blockIdx.y * 128;
    int arow = tid >> 1,  acol = (tid & 1) * 4;
    int brow = tid >> 5,  bcol = (tid & 31) * 4;
    int ty   = tid >> 4,  tx   = tid & 15;

    const float* Ap = A + (size_t)(by + arow) * Kdim + acol;
    const float* Wp = W + (size_t)brow * Ndim + bx + bcol;

    float acc[8][8];
    #pragma unroll
    for (int i = 0; i < 8; i++)
        #pragma unroll
        for (int j = 0; j < 8; j++) acc[i][j] = 0.f;

    for (int k0 = 0; k0 < Kdim; k0 += 8) {
        float4 av = *(const float4*)(Ap + k0);
        float4 bv = *(const float4*)(Wp + (size_t)k0 * Ndim);
        As[acol + 0][arow] = av.x;
        As[acol + 1][arow] = av.y;
        As[acol + 2][arow] = av.z;
        As[acol + 3][arow] = av.w;
        *(float4*)&Bs[brow][bcol] = bv;
        __syncthreads();

        #pragma unroll
        for (int kk = 0; kk < 8; kk++) {
            float a[8], b[8];
            *(float4*)(a)     = *(float4*)&As[kk][ty * 8];
            *(float4*)(a + 4) = *(float4*)&As[kk][ty * 8 + 4];
            *(float4*)(b)     = *(float4*)&Bs[kk][tx * 8];
            *(float4*)(b + 4) = *(float4*)&Bs[kk][tx * 8 + 4];
            #pragma unroll
            for (int i = 0; i < 8; i++)
                #pragma unroll
                for (int j = 0; j < 8; j++)
                    acc[i][j] += a[i] * b[j];
        }
        __syncthreads();
    }

    float4 bia0 = *(const float4*)&bias[bx + tx * 8];
    float4 bia1 = *(const float4*)&bias[bx + tx * 8 + 4];
    #pragma unroll
    for (int i = 0; i < 8; i++) {
        float* Cp = C + (size_t)(by + ty * 8 + i) * Ndim + bx + tx * 8;
        float4 r0, r1;
        r0.x = acc[i][0] + bia0.x; r0.y = acc[i][1] + bia0.y;
        r0.z = acc[i][2] + bia0.z; r0.w = acc[i][3] + bia0.w;
        r1.x = acc[i][4] + bia1.x; r1.y = acc[i][5] + bia1.y;
        r1.z = acc[i][6] + bia1.z; r1.w = acc[i][7] + bia1.w;
        *(float4*)Cp       = r0;
        *(float4*)(Cp + 4) = r1;
    }
}

// ---------------- Flash attention (causal, fp32) ----------------
// Block: 64 queries x full Dh=128, 256 threads. K-tiles of 64.
// smem: Q[64*128] K[64*128] V[64*128] S[64*65] m/l/c[64 each] = 115712 bytes
#define ATTN_SMEM ((3 * 64 * 128 + 64 * 65 + 3 * 64) * 4)

__global__ __launch_bounds__(256) void attn_kernel(
    const float* __restrict__ Q, const float* __restrict__ K,
    const float* __restrict__ V, float* __restrict__ AV)
{
    extern __shared__ float sm[];
    float* Qs   = sm;
    float* Ks   = Qs + 64 * 128;
    float* Vs   = Ks + 64 * 128;
    float* Ss   = Vs + 64 * 128;       // stride 65 (conflict-free row scans)
    float* mrow = Ss + 64 * 65;
    float* lrow = mrow + 64;
    float* crow = lrow + 64;

    int tid = threadIdx.x;
    int qt  = blockIdx.x;
    int bh  = blockIdx.y;
    int b   = bh >> 4, h = bh & 15;
    int q0  = qt * 64;
    int ty  = tid >> 4, tx = tid & 15;

    const float* Qg = Q + (size_t)(b * S_LEN + q0) * D_MODEL + h * D_HEAD;
    #pragma unroll
    for (int i = 0; i < 8; i++) {
        int lin = tid + i * 256;            // float4 index into 64x128 tile
        int r = lin >> 5, c4 = lin & 31;
        ((float4*)Qs)[lin] = *(const float4*)(Qg + (size_t)r * D_MODEL + c4 * 4);
    }
    if (tid < 64) { mrow[tid] = -1e30f; lrow[tid] = 0.f; }

    float o[4][8];
    #pragma unroll
    for (int i = 0; i < 4; i++)
        #pragma unroll
        for (int j = 0; j < 8; j++) o[i][j] = 0.f;
    __syncthreads();

    const float scale = 0.08838834764831845f;   // 1/sqrt(128)

    for (int kt = 0; kt <= qt; kt++) {
        int k0 = kt * 64;
        const float* Kg = K + (size_t)(b * S_LEN + k0) * D_MODEL + h * D_HEAD;
        const float* Vg = V + (size_t)(b * S_LEN + k0) * D_MODEL + h * D_HEAD;
        #pragma unroll
        for (int i = 0; i < 8; i++) {
            int lin = tid + i * 256;
            int r = lin >> 5, c4 = lin & 31;
            ((float4*)Ks)[lin] = *(const float4*)(Kg + (size_t)r * D_MODEL + c4 * 4);
            ((float4*)Vs)[lin] = *(const float4*)(Vg + (size_t)r * D_MODEL + c4 * 4);
        }
        __syncthreads();

        // scores: 4q x 4k per thread
        float sc[4][4];
        #pragma unroll
        for (int i = 0; i < 4; i++)
            #pragma unroll
            for (int j = 0; j < 4; j++) sc[i][j] = 0.f;

        for (int kk = 0; kk < 128; kk += 4) {
            float4 qv[4], kv[4];
            #pragma unroll
            for (int i = 0; i < 4; i++) qv[i] = *(float4*)&Qs[(ty * 4 + i) * 128 + kk];
            #pragma unroll
            for (int j = 0; j < 4; j++) kv[j] = *(float4*)&Ks[(tx * 4 + j) * 128 + kk];
            #pragma unroll
            for (int i = 0; i < 4; i++)
                #pragma unroll
                for (int j = 0; j < 4; j++)
                    sc[i][j] += qv[i].x * kv[j].x + qv[i].y * kv[j].y
                              + qv[i].z * kv[j].z + qv[i].w * kv[j].w;
        }
        #pragma unroll
        for (int i = 0; i < 4; i++) {
            int qg = q0 + ty * 4 + i;
            #pragma unroll
            for (int j = 0; j < 4; j++) {
                int kg = k0 + tx * 4 + j;
                float v = sc[i][j] * scale;
                if (kg > qg) v = -1e30f;
                Ss[(ty * 4 + i) * 65 + tx * 4 + j] = v;
            }
        }
        __syncthreads();

        // online softmax per row (threads 0..63)
        if (tid < 64) {
            float* srow = Ss + tid * 65;
            float mold = mrow[tid];
            float mx = mold;
            #pragma unroll 8
            for (int k = 0; k < 64; k++) mx = fmaxf(mx, srow[k]);
            float c = __expf(mold - mx);
            float sum = 0.f;
            #pragma unroll 8
            for (int k = 0; k < 64; k++) {
                float p = __expf(srow[k] - mx);
                srow[k] = p;
                sum += p;
            }
            mrow[tid] = mx;
            lrow[tid] = lrow[tid] * c + sum;
            crow[tid] = c;
        }
        __syncthreads();

        // P @ V : 4q x 8d per thread (d = tx*8)
        #pragma unroll
        for (int i = 0; i < 4; i++) {
            float c = crow[ty * 4 + i];
            #pragma unroll
            for (int j = 0; j < 8; j++) o[i][j] *= c;
        }
        for (int k = 0; k < 64; k++) {
            float p0 = Ss[(ty * 4 + 0) * 65 + k];
            float p1 = Ss[(ty * 4 + 1) * 65 + k];
            float p2 = Ss[(ty * 4 + 2) * 65 + k];
            float p3 = Ss[(ty * 4 + 3) * 65 + k];
            float4 va = *(float4*)&Vs[k * 128 + tx * 8];
            float4 vb = *(float4*)&Vs[k * 128 + tx * 8 + 4];
            o[0][0] += p0 * va.x; o[0][1] += p0 * va.y; o[0][2] += p0 * va.z; o[0][3] += p0 * va.w;
            o[0][4] += p0 * vb.x; o[0][5] += p0 * vb.y; o[0][6] += p0 * vb.z; o[0][7] += p0 * vb.w;
            o[1][0] += p1 * va.x; o[1][1] += p1 * va.y; o[1][2] += p1 * va.z; o[1][3] += p1 * va.w;
            o[1][4] += p1 * vb.x; o[1][5] += p1 * vb.y; o[1][6] += p1 * vb.z; o[1][7] += p1 * vb.w;
            o[2][0] += p2 * va.x; o[2][1] += p2 * va.y; o[2][2] += p2 * va.z; o[2][3] += p2 * va.w;
            o[2][4] += p2 * vb.x; o[2][5] += p2 * vb.y; o[2][6] += p2 * vb.z; o[2][7] += p2 * vb.w;
            o[3][0] += p3 * va.x; o[3][1] += p3 * va.y; o[3][2] += p3 * va.z; o[3][3] += p3 * va.w;
            o[3][4] += p3 * vb.x; o[3][5] += p3 * vb.y; o[3][6] += p3 * vb.z; o[3][7] += p3 * vb.w;
        }
        __syncthreads();
    }

    // normalize and write
    #pragma unroll
    for (int i = 0; i < 4; i++) {
        float inv = 1.f / lrow[ty * 4 + i];
        float* dst = AV + (size_t)(b * S_LEN + q0 + ty * 4 + i) * D_MODEL + h * D_HEAD + tx * 8;
        float4 r0, r1;
        r0.x = o[i][0] * inv; r0.y = o[i][1] * inv; r0.z = o[i][2] * inv; r0.w = o[i][3] * inv;
        r1.x = o[i][4] * inv; r1.y = o[i][5] * inv; r1.z = o[i][6] * inv; r1.w = o[i][7] * inv;
        *(float4*)dst       = r0;
        *(float4*)(dst + 4) = r1;
    }
}

// ---------------- launch ----------------
extern "C" void kernel_launch(void* const* d_in, const int* in_sizes, int n_in,
                              void* d_out, int out_size)
{
    const float* X    = (const float*)d_in[0];
    const float* ln_g = (const float*)d_in[1];
    const float* ln_b = (const float*)d_in[2];
    const float* Wq   = (const float*)d_in[3];
    const float* bq   = (const float*)d_in[4];
    const float* Wk   = (const float*)d_in[5];
    const float* bk   = (const float*)d_in[6];
    const float* Wv   = (const float*)d_in[7];
    const float* bv   = (const float*)d_in[8];
    const float* Wo   = (const float*)d_in[9];
    const float* bo   = (const float*)d_in[10];
    float* out = (float*)d_out;

    float *Xn, *Q, *Kd, *Vd, *AV;
    cudaGetSymbolAddress((void**)&Xn, g_Xn);
    cudaGetSymbolAddress((void**)&Q,  g_Q);
    cudaGetSymbolAddress((void**)&Kd, g_K);
    cudaGetSymbolAddress((void**)&Vd, g_V);
    cudaGetSymbolAddress((void**)&AV, g_AV);

    ln_kernel<<<NROWS, 256>>>(X, ln_g, ln_b, Xn);

    dim3 gg(D_MODEL / 128, NROWS / 128);
    sgemm_bias<<<gg, 256>>>(Xn, Wq, bq, Q);
    sgemm_bias<<<gg, 256>>>(Xn, Wk, bk, Kd);
    sgemm_bias<<<gg, 256>>>(Xn, Wv, bv, Vd);

    cudaFuncSetAttribute(attn_kernel, cudaFuncAttributeMaxDynamicSharedMemorySize, ATTN_SMEM);
    attn_kernel<<<dim3(S_LEN / 64, BATCH * N_HEADS), 256, ATTN_SMEM>>>(Q, Kd, Vd, AV);

    sgemm_bias<<<gg, 256>>>(AV, Wo, bo, out);
}

// round 7
// speedup vs baseline: 1.4862x; 1.4862x over previous
#include <cuda_runtime.h>
#include <cuda_bf16.h>
#include <math.h>
#include <cstdint>

#define D_MODEL 2048
#define S_LEN   2048
#define BATCH   2
#define NROWS   (BATCH * S_LEN)   // 4096
#define N_HEADS 16
#define D_HEAD  128

// ---------------- scratch (alloc-free rule: __device__ globals) ----------------
__device__ float g_Q [(size_t)NROWS * D_MODEL];
__device__ float g_K [(size_t)NROWS * D_MODEL];
__device__ float g_V [(size_t)NROWS * D_MODEL];
__device__ float g_AV[(size_t)NROWS * D_MODEL];

__device__ __nv_bfloat16 g_Xh [(size_t)NROWS * D_MODEL];
__device__ __nv_bfloat16 g_Xl [(size_t)NROWS * D_MODEL];
__device__ __nv_bfloat16 g_AVh[(size_t)NROWS * D_MODEL];
__device__ __nv_bfloat16 g_AVl[(size_t)NROWS * D_MODEL];
// transposed weight splits: [4][N=2048][K=2048], order: Wq, Wk, Wv, Wo
__device__ __nv_bfloat16 g_Wth[(size_t)4 * D_MODEL * D_MODEL];
__device__ __nv_bfloat16 g_Wtl[(size_t)4 * D_MODEL * D_MODEL];

// ---------------- PTX helpers (all valid on plain sm_103 target) ----------------
__device__ __forceinline__ uint32_t smem_u32(const void* p) {
    uint32_t a;
    asm("{ .reg .u64 t; cvta.to.shared.u64 t, %1; cvt.u32.u64 %0, t; }" : "=r"(a) : "l"(p));
    return a;
}
#define SWZ128(off) ((off) ^ (((off) >> 3) & 0x70))

__device__ __forceinline__ void cp_async16(uint32_t saddr, const void* gaddr) {
    asm volatile("cp.async.cg.shared.global [%0], [%1], 16;\n" :: "r"(saddr), "l"(gaddr));
}
#define CP_COMMIT() asm volatile("cp.async.commit_group;\n" ::: "memory")
#define CP_WAIT3()  asm volatile("cp.async.wait_group 3;\n" ::: "memory")

__device__ __forceinline__ void ldmx4(uint32_t* r, uint32_t addr) {
    asm volatile("ldmatrix.sync.aligned.m8n8.x4.shared.b16 {%0,%1,%2,%3}, [%4];"
        : "=r"(r[0]), "=r"(r[1]), "=r"(r[2]), "=r"(r[3]) : "r"(addr));
}
__device__ __forceinline__ void mma16816(float* d, const uint32_t* a, const uint32_t* b) {
    asm volatile(
        "mma.sync.aligned.m16n8k16.row.col.f32.bf16.bf16.f32 "
        "{%0,%1,%2,%3}, {%4,%5,%6,%7}, {%8,%9}, {%0,%1,%2,%3};"
        : "+f"(d[0]), "+f"(d[1]), "+f"(d[2]), "+f"(d[3])
        : "r"(a[0]), "r"(a[1]), "r"(a[2]), "r"(a[3]), "r"(b[0]), "r"(b[1]));
}

// ---------------- LayerNorm + bf16 split: one block per row ----------------
__global__ __launch_bounds__(256) void ln_split_kernel(
    const float* __restrict__ X, const float* __restrict__ gam,
    const float* __restrict__ bet, __nv_bfloat16* __restrict__ Xh,
    __nv_bfloat16* __restrict__ Xl)
{
    int row = blockIdx.x;
    const float4* x4 = (const float4*)(X + (size_t)row * D_MODEL);
    const float4* g4 = (const float4*)gam;
    const float4* b4 = (const float4*)bet;
    int tid = threadIdx.x;

    float4 v0 = x4[tid];
    float4 v1 = x4[tid + 256];
    float s  = v0.x + v0.y + v0.z + v0.w + v1.x + v1.y + v1.z + v1.w;
    float ss = v0.x*v0.x + v0.y*v0.y + v0.z*v0.z + v0.w*v0.w
             + v1.x*v1.x + v1.y*v1.y + v1.z*v1.z + v1.w*v1.w;

    #pragma unroll
    for (int off = 16; off; off >>= 1) {
        s  += __shfl_xor_sync(0xffffffffu, s,  off);
        ss += __shfl_xor_sync(0xffffffffu, ss, off);
    }
    __shared__ float rs[8], rss[8];
    __shared__ float s_mean, s_rstd;
    int w = tid >> 5, l = tid & 31;
    if (l == 0) { rs[w] = s; rss[w] = ss; }
    __syncthreads();
    if (tid == 0) {
        float t = 0.f, tt = 0.f;
        #pragma unroll
        for (int i = 0; i < 8; i++) { t += rs[i]; tt += rss[i]; }
        float mean = t * (1.f / D_MODEL);
        float var  = tt * (1.f / D_MODEL) - mean * mean;
        s_mean = mean;
        s_rstd = rsqrtf(var + 1e-5f);
    }
    __syncthreads();
    float mean = s_mean, rstd = s_rstd;

    float4 g0 = g4[tid], g1 = g4[tid + 256];
    float4 c0 = b4[tid], c1 = b4[tid + 256];
    float r[8];
    r[0] = (v0.x - mean) * rstd * g0.x + c0.x;
    r[1] = (v0.y - mean) * rstd * g0.y + c0.y;
    r[2] = (v0.z - mean) * rstd * g0.z + c0.z;
    r[3] = (v0.w - mean) * rstd * g0.w + c0.w;
    r[4] = (v1.x - mean) * rstd * g1.x + c1.x;
    r[5] = (v1.y - mean) * rstd * g1.y + c1.y;
    r[6] = (v1.z - mean) * rstd * g1.z + c1.z;
    r[7] = (v1.w - mean) * rstd * g1.w + c1.w;

    __nv_bfloat16 hi0[4], lo0[4], hi1[4], lo1[4];
    #pragma unroll
    for (int i = 0; i < 4; i++) {
        hi0[i] = __float2bfloat16(r[i]);
        lo0[i] = __float2bfloat16(r[i] - __bfloat162float(hi0[i]));
        hi1[i] = __float2bfloat16(r[i + 4]);
        lo1[i] = __float2bfloat16(r[i + 4] - __bfloat162float(hi1[i]));
    }
    size_t base = (size_t)row * D_MODEL;
    *(uint2*)(Xh + base + tid * 4)            = *(uint2*)hi0;
    *(uint2*)(Xh + base + (tid + 256) * 4)    = *(uint2*)hi1;
    *(uint2*)(Xl + base + tid * 4)            = *(uint2*)lo0;
    *(uint2*)(Xl + base + (tid + 256) * 4)    = *(uint2*)lo1;
}

// ---------------- weight transpose + split: W[K,N] -> Wt_h/Wt_l [N,K] ----------------
__global__ __launch_bounds__(256) void transpose_split_kernel(
    const float* __restrict__ W, __nv_bfloat16* __restrict__ Th,
    __nv_bfloat16* __restrict__ Tl)
{
    __shared__ float t[32][33];
    int bx = blockIdx.x * 32;   // n0
    int by = blockIdx.y * 32;   // k0
    int tx = threadIdx.x & 31, ty = threadIdx.x >> 5;  // ty in 0..7
    #pragma unroll
    for (int r = 0; r < 4; r++)
        t[ty + r * 8][tx] = W[(size_t)(by + ty + r * 8) * D_MODEL + bx + tx];
    __syncthreads();
    #pragma unroll
    for (int r = 0; r < 4; r++) {
        float v = t[tx][ty + r * 8];
        __nv_bfloat16 h = __float2bfloat16(v);
        size_t idx = (size_t)(bx + ty + r * 8) * D_MODEL + by + tx;
        Th[idx] = h;
        Tl[idx] = __float2bfloat16(v - __bfloat162float(h));
    }
}

// ---------------- fp32 -> bf16 hi/lo split (for AV) ----------------
__global__ __launch_bounds__(256) void split_kernel(
    const float* __restrict__ A, __nv_bfloat16* __restrict__ H,
    __nv_bfloat16* __restrict__ L)
{
    size_t i = ((size_t)blockIdx.x * 256 + threadIdx.x) * 4;
    float4 v = *(const float4*)(A + i);
    __nv_bfloat16 h[4], l[4];
    float f[4] = {v.x, v.y, v.z, v.w};
    #pragma unroll
    for (int j = 0; j < 4; j++) {
        h[j] = __float2bfloat16(f[j]);
        l[j] = __float2bfloat16(f[j] - __bfloat162float(h[j]));
    }
    *(uint2*)(H + i) = *(uint2*)h;
    *(uint2*)(L + i) = *(uint2*)l;
}

// ---------------- HMMA bf16x3 GEMM: C[M,N] = (Ah+Al)[M,K] @ (Bh+Bl)^T + bias ----------------
// A: [4096, 2048] bf16 K-major.  B (weightT): [2048(n), 2048(k)] bf16 K-major.
// CTA tile 128x128, BK=64, 4-stage cp.async pipeline, 3 passes (AhBh, AlBh, AhBl).
// 8 warps: 2 (m) x 4 (n); warp tile 64x32; mma.sync m16n8k16.
#define GDEPTH 4
#define STAGE_BYTES 32768          // A tile 16KB + B tile 16KB (SW128 rows of 128B)
#define GEMM_SMEM (GDEPTH * STAGE_BYTES)
#define NKITER 32                  // 2048 / 64
#define NITER  (3 * NKITER)        // 96

__global__ __launch_bounds__(256) void gemm_hmma(
    const __nv_bfloat16* __restrict__ Ah, const __nv_bfloat16* __restrict__ Al,
    const __nv_bfloat16* __restrict__ Bh, const __nv_bfloat16* __restrict__ Bl,
    const float* __restrict__ bias, float* __restrict__ C)
{
    extern __shared__ __align__(1024) char smc[];
    uint32_t sbase = smem_u32(smc);
    int tid  = threadIdx.x;
    int wid  = tid >> 5;
    int lane = tid & 31;

    int bx = blockIdx.x * 128;   // N
    int by = blockIdx.y * 128;   // M
    int wm = wid & 1;            // m block of 64
    int wn = wid >> 1;           // n block of 32

    const __nv_bfloat16* Asrc[3] = {Ah, Al, Ah};
    const __nv_bfloat16* Bsrc[3] = {Bh, Bh, Bl};

    float acc[4][4][4];          // [mt][ntt][frag]
    #pragma unroll
    for (int i = 0; i < 4; i++)
        #pragma unroll
        for (int j = 0; j < 4; j++)
            #pragma unroll
            for (int k = 0; k < 4; k++) acc[i][j][k] = 0.f;

    // ldmatrix lane-address components
    int lr = lane & 7, g = lane >> 3;
    int a_row = wm * 64 + ((g & 1) << 3) + lr;     // + mt*16
    int a_col = (g >> 1) << 4;                     // byte col + ks*32
    int b_row = wn * 32 + ((g >> 1) << 3) + lr;    // + nt*16
    int b_col = (g & 1) << 4;                      // byte col + ks*32

    auto issue = [&](int it) {
        int p  = it >> 5;                 // pass 0..2
        int k0 = (it & (NKITER - 1)) * 64;
        int s  = it & (GDEPTH - 1);
        uint32_t sa = sbase + s * STAGE_BYTES;
        uint32_t sb = sa + 16384;
        const __nv_bfloat16* Ap = Asrc[p];
        const __nv_bfloat16* Bp = Bsrc[p];
        #pragma unroll
        for (int j = 0; j < 4; j++) {
            int c = tid + j * 256;            // 0..1023
            int r = c >> 3, c16 = c & 7;      // tile row, 16B chunk
            uint32_t off = SWZ128((uint32_t)(r * 128 + c16 * 16));
            cp_async16(sa + off, Ap + (size_t)(by + r) * D_MODEL + k0 + c16 * 8);
            cp_async16(sb + off, Bp + (size_t)(bx + r) * D_MODEL + k0 + c16 * 8);
        }
        CP_COMMIT();
    };

    issue(0); issue(1); issue(2);

    for (int i = 0; i < NITER; i++) {
        if (i + 3 < NITER) issue(i + 3); else CP_COMMIT();
        CP_WAIT3();
        __syncthreads();

        int s = i & (GDEPTH - 1);
        uint32_t sa = sbase + s * STAGE_BYTES;
        uint32_t sb = sa + 16384;

        #pragma unroll
        for (int ks = 0; ks < 4; ks++) {
            uint32_t afr[4][4], bfr[2][4];
            #pragma unroll
            for (int mt = 0; mt < 4; mt++)
                ldmx4(afr[mt], sa + SWZ128((uint32_t)((a_row + mt * 16) * 128 + ks * 32 + a_col)));
            #pragma unroll
            for (int nt = 0; nt < 2; nt++)
                ldmx4(bfr[nt], sb + SWZ128((uint32_t)((b_row + nt * 16) * 128 + ks * 32 + b_col)));
            #pragma unroll
            for (int mt = 0; mt < 4; mt++) {
                #pragma unroll
                for (int nt = 0; nt < 2; nt++) {
                    mma16816(acc[mt][nt * 2],     afr[mt], bfr[nt]);
                    mma16816(acc[mt][nt * 2 + 1], afr[mt], bfr[nt] + 2);
                }
            }
        }
        __syncthreads();   // stage s reusable by the issue at iteration i+1
    }

    // epilogue: m16n8 fragment layout -> C + bias
    int qrow = lane >> 2;
    int qcol = (lane & 3) * 2;
    #pragma unroll
    for (int mt = 0; mt < 4; mt++) {
        int m0 = by + wm * 64 + mt * 16 + qrow;
        #pragma unroll
        for (int ntt = 0; ntt < 4; ntt++) {
            int n = bx + wn * 32 + ntt * 8 + qcol;
            float2 bv = *(const float2*)&bias[n];
            float2 r0, r1;
            r0.x = acc[mt][ntt][0] + bv.x;
            r0.y = acc[mt][ntt][1] + bv.y;
            r1.x = acc[mt][ntt][2] + bv.x;
            r1.y = acc[mt][ntt][3] + bv.y;
            *(float2*)&C[(size_t)m0 * D_MODEL + n]       = r0;
            *(float2*)&C[(size_t)(m0 + 8) * D_MODEL + n] = r1;
        }
    }
}

// ---------------- Flash attention (causal, fp32) — unchanged from R1 ----------------
#define ATTN_SMEM ((3 * 64 * 128 + 64 * 65 + 3 * 64) * 4)

__global__ __launch_bounds__(256) void attn_kernel(
    const float* __restrict__ Q, const float* __restrict__ K,
    const float* __restrict__ V, float* __restrict__ AV)
{
    extern __shared__ float smf[];
    float* Qs   = smf;
    float* Ks   = Qs + 64 * 128;
    float* Vs   = Ks + 64 * 128;
    float* Ss   = Vs + 64 * 128;
    float* mrow = Ss + 64 * 65;
    float* lrow = mrow + 64;
    float* crow = lrow + 64;

    int tid = threadIdx.x;
    int qt  = blockIdx.x;
    int bh  = blockIdx.y;
    int b   = bh >> 4, h = bh & 15;
    int q0  = qt * 64;
    int ty  = tid >> 4, tx = tid & 15;

    const float* Qg = Q + (size_t)(b * S_LEN + q0) * D_MODEL + h * D_HEAD;
    #pragma unroll
    for (int i = 0; i < 8; i++) {
        int lin = tid + i * 256;
        int r = lin >> 5, c4 = lin & 31;
        ((float4*)Qs)[lin] = *(const float4*)(Qg + (size_t)r * D_MODEL + c4 * 4);
    }
    if (tid < 64) { mrow[tid] = -1e30f; lrow[tid] = 0.f; }

    float o[4][8];
    #pragma unroll
    for (int i = 0; i < 4; i++)
        #pragma unroll
        for (int j = 0; j < 8; j++) o[i][j] = 0.f;
    __syncthreads();

    const float scale = 0.08838834764831845f;

    for (int kt = 0; kt <= qt; kt++) {
        int k0 = kt * 64;
        const float* Kg = K + (size_t)(b * S_LEN + k0) * D_MODEL + h * D_HEAD;
        const float* Vg = V + (size_t)(b * S_LEN + k0) * D_MODEL + h * D_HEAD;
        #pragma unroll
        for (int i = 0; i < 8; i++) {
            int lin = tid + i * 256;
            int r = lin >> 5, c4 = lin & 31;
            ((float4*)Ks)[lin] = *(const float4*)(Kg + (size_t)r * D_MODEL + c4 * 4);
            ((float4*)Vs)[lin] = *(const float4*)(Vg + (size_t)r * D_MODEL + c4 * 4);
        }
        __syncthreads();

        float sc[4][4];
        #pragma unroll
        for (int i = 0; i < 4; i++)
            #pragma unroll
            for (int j = 0; j < 4; j++) sc[i][j] = 0.f;

        for (int kk = 0; kk < 128; kk += 4) {
            float4 qv[4], kv[4];
            #pragma unroll
            for (int i = 0; i < 4; i++) qv[i] = *(float4*)&Qs[(ty * 4 + i) * 128 + kk];
            #pragma unroll
            for (int j = 0; j < 4; j++) kv[j] = *(float4*)&Ks[(tx * 4 + j) * 128 + kk];
            #pragma unroll
            for (int i = 0; i < 4; i++)
                #pragma unroll
                for (int j = 0; j < 4; j++)
                    sc[i][j] += qv[i].x * kv[j].x + qv[i].y * kv[j].y
                              + qv[i].z * kv[j].z + qv[i].w * kv[j].w;
        }
        #pragma unroll
        for (int i = 0; i < 4; i++) {
            int qg = q0 + ty * 4 + i;
            #pragma unroll
            for (int j = 0; j < 4; j++) {
                int kg = k0 + tx * 4 + j;
                float v = sc[i][j] * scale;
                if (kg > qg) v = -1e30f;
                Ss[(ty * 4 + i) * 65 + tx * 4 + j] = v;
            }
        }
        __syncthreads();

        if (tid < 64) {
            float* srow = Ss + tid * 65;
            float mold = mrow[tid];
            float mx = mold;
            #pragma unroll 8
            for (int k = 0; k < 64; k++) mx = fmaxf(mx, srow[k]);
            float c = __expf(mold - mx);
            float sum = 0.f;
            #pragma unroll 8
            for (int k = 0; k < 64; k++) {
                float p = __expf(srow[k] - mx);
                srow[k] = p;
                sum += p;
            }
            mrow[tid] = mx;
            lrow[tid] = lrow[tid] * c + sum;
            crow[tid] = c;
        }
        __syncthreads();

        #pragma unroll
        for (int i = 0; i < 4; i++) {
            float c = crow[ty * 4 + i];
            #pragma unroll
            for (int j = 0; j < 8; j++) o[i][j] *= c;
        }
        for (int k = 0; k < 64; k++) {
            float p0 = Ss[(ty * 4 + 0) * 65 + k];
            float p1 = Ss[(ty * 4 + 1) * 65 + k];
            float p2 = Ss[(ty * 4 + 2) * 65 + k];
            float p3 = Ss[(ty * 4 + 3) * 65 + k];
            float4 va = *(float4*)&Vs[k * 128 + tx * 8];
            float4 vb = *(float4*)&Vs[k * 128 + tx * 8 + 4];
            o[0][0] += p0 * va.x; o[0][1] += p0 * va.y; o[0][2] += p0 * va.z; o[0][3] += p0 * va.w;
            o[0][4] += p0 * vb.x; o[0][5] += p0 * vb.y; o[0][6] += p0 * vb.z; o[0][7] += p0 * vb.w;
            o[1][0] += p1 * va.x; o[1][1] += p1 * va.y; o[1][2] += p1 * va.z; o[1][3] += p1 * va.w;
            o[1][4] += p1 * vb.x; o[1][5] += p1 * vb.y; o[1][6] += p1 * vb.z; o[1][7] += p1 * vb.w;
            o[2][0] += p2 * va.x; o[2][1] += p2 * va.y; o[2][2] += p2 * va.z; o[2][3] += p2 * va.w;
            o[2][4] += p2 * vb.x; o[2][5] += p2 * vb.y; o[2][6] += p2 * vb.z; o[2][7] += p2 * vb.w;
            o[3][0] += p3 * va.x; o[3][1] += p3 * va.y; o[3][2] += p3 * va.z; o[3][3] += p3 * va.w;
            o[3][4] += p3 * vb.x; o[3][5] += p3 * vb.y; o[3][6] += p3 * vb.z; o[3][7] += p3 * vb.w;
        }
        __syncthreads();
    }

    #pragma unroll
    for (int i = 0; i < 4; i++) {
        float inv = 1.f / lrow[ty * 4 + i];
        float* dst = AV + (size_t)(b * S_LEN + q0 + ty * 4 + i) * D_MODEL + h * D_HEAD + tx * 8;
        float4 r0, r1;
        r0.x = o[i][0] * inv; r0.y = o[i][1] * inv; r0.z = o[i][2] * inv; r0.w = o[i][3] * inv;
        r1.x = o[i][4] * inv; r1.y = o[i][5] * inv; r1.z = o[i][6] * inv; r1.w = o[i][7] * inv;
        *(float4*)dst       = r0;
        *(float4*)(dst + 4) = r1;
    }
}

// ---------------- launch ----------------
extern "C" void kernel_launch(void* const* d_in, const int* in_sizes, int n_in,
                              void* d_out, int out_size)
{
    const float* X    = (const float*)d_in[0];
    const float* ln_g = (const float*)d_in[1];
    const float* ln_b = (const float*)d_in[2];
    const float* Wq   = (const float*)d_in[3];
    const float* bq   = (const float*)d_in[4];
    const float* Wk   = (const float*)d_in[5];
    const float* bk   = (const float*)d_in[6];
    const float* Wv   = (const float*)d_in[7];
    const float* bv   = (const float*)d_in[8];
    const float* Wo   = (const float*)d_in[9];
    const float* bo   = (const float*)d_in[10];
    float* out = (float*)d_out;

    float *Q, *Kd, *Vd, *AV;
    __nv_bfloat16 *Xh, *Xl, *AVh, *AVl, *Wth, *Wtl;
    cudaGetSymbolAddress((void**)&Q,   g_Q);
    cudaGetSymbolAddress((void**)&Kd,  g_K);
    cudaGetSymbolAddress((void**)&Vd,  g_V);
    cudaGetSymbolAddress((void**)&AV,  g_AV);
    cudaGetSymbolAddress((void**)&Xh,  g_Xh);
    cudaGetSymbolAddress((void**)&Xl,  g_Xl);
    cudaGetSymbolAddress((void**)&AVh, g_AVh);
    cudaGetSymbolAddress((void**)&AVl, g_AVl);
    cudaGetSymbolAddress((void**)&Wth, g_Wth);
    cudaGetSymbolAddress((void**)&Wtl, g_Wtl);

    const size_t WSZ = (size_t)D_MODEL * D_MODEL;

    // transpose + bf16-split all four weights
    dim3 tg(D_MODEL / 32, D_MODEL / 32);
    transpose_split_kernel<<<tg, 256>>>(Wq, Wth + 0 * WSZ, Wtl + 0 * WSZ);
    transpose_split_kernel<<<tg, 256>>>(Wk, Wth + 1 * WSZ, Wtl + 1 * WSZ);
    transpose_split_kernel<<<tg, 256>>>(Wv, Wth + 2 * WSZ, Wtl + 2 * WSZ);
    transpose_split_kernel<<<tg, 256>>>(Wo, Wth + 3 * WSZ, Wtl + 3 * WSZ);

    // LayerNorm + split
    ln_split_kernel<<<NROWS, 256>>>(X, ln_g, ln_b, Xh, Xl);

    // QKV projections on tensor cores (HMMA)
    cudaFuncSetAttribute(gemm_hmma, cudaFuncAttributeMaxDynamicSharedMemorySize, GEMM_SMEM);
    dim3 gg(D_MODEL / 128, NROWS / 128);
    gemm_hmma<<<gg, 256, GEMM_SMEM>>>(Xh, Xl, Wth + 0 * WSZ, Wtl + 0 * WSZ, bq, Q);
    gemm_hmma<<<gg, 256, GEMM_SMEM>>>(Xh, Xl, Wth + 1 * WSZ, Wtl + 1 * WSZ, bk, Kd);
    gemm_hmma<<<gg, 256, GEMM_SMEM>>>(Xh, Xl, Wth + 2 * WSZ, Wtl + 2 * WSZ, bv, Vd);

    // attention
    cudaFuncSetAttribute(attn_kernel, cudaFuncAttributeMaxDynamicSharedMemorySize, ATTN_SMEM);
    attn_kernel<<<dim3(S_LEN / 64, BATCH * N_HEADS), 256, ATTN_SMEM>>>(Q, Kd, Vd, AV);

    // split AV, output projection
    split_kernel<<<(NROWS * D_MODEL) / (256 * 4), 256>>>(AV, AVh, AVl);
    gemm_hmma<<<gg, 256, GEMM_SMEM>>>(AVh, AVl, Wth + 3 * WSZ, Wtl + 3 * WSZ, bo, out);
}

// round 8
// speedup vs baseline: 2.7241x; 1.8329x over previous
#include <cuda_runtime.h>
#include <cuda_bf16.h>
#include <math.h>
#include <cstdint>

#define D_MODEL 2048
#define S_LEN   2048
#define BATCH   2
#define NROWS   (BATCH * S_LEN)   // 4096
#define N_HEADS 16
#define D_HEAD  128

// ---------------- scratch (alloc-free rule: __device__ globals) ----------------
__device__ __nv_bfloat16 g_Xh [(size_t)NROWS * D_MODEL];
__device__ __nv_bfloat16 g_Xl [(size_t)NROWS * D_MODEL];
__device__ __nv_bfloat16 g_Qh [(size_t)NROWS * D_MODEL];
__device__ __nv_bfloat16 g_Ql [(size_t)NROWS * D_MODEL];
__device__ __nv_bfloat16 g_Kh [(size_t)NROWS * D_MODEL];
__device__ __nv_bfloat16 g_Kl [(size_t)NROWS * D_MODEL];
__device__ __nv_bfloat16 g_Vh [(size_t)NROWS * D_MODEL];
__device__ __nv_bfloat16 g_Vl [(size_t)NROWS * D_MODEL];
__device__ __nv_bfloat16 g_AVh[(size_t)NROWS * D_MODEL];
__device__ __nv_bfloat16 g_AVl[(size_t)NROWS * D_MODEL];
// transposed weight splits: [4][N=2048][K=2048], order: Wq, Wk, Wv, Wo
__device__ __nv_bfloat16 g_Wth[(size_t)4 * D_MODEL * D_MODEL];
__device__ __nv_bfloat16 g_Wtl[(size_t)4 * D_MODEL * D_MODEL];

// ---------------- PTX helpers (valid on plain sm_103 target) ----------------
__device__ __forceinline__ uint32_t smem_u32(const void* p) {
    uint32_t a;
    asm("{ .reg .u64 t; cvta.to.shared.u64 t, %1; cvt.u32.u64 %0, t; }" : "=r"(a) : "l"(p));
    return a;
}
#define SWZ128(off) ((off) ^ (((off) >> 3) & 0x70))

__device__ __forceinline__ void cp_async16(uint32_t saddr, const void* gaddr) {
    asm volatile("cp.async.cg.shared.global [%0], [%1], 16;\n" :: "r"(saddr), "l"(gaddr));
}
#define CP_COMMIT() asm volatile("cp.async.commit_group;\n" ::: "memory")
#define CP_WAIT0()  asm volatile("cp.async.wait_group 0;\n" ::: "memory")
#define CP_WAIT1()  asm volatile("cp.async.wait_group 1;\n" ::: "memory")
#define CP_WAIT3()  asm volatile("cp.async.wait_group 3;\n" ::: "memory")

__device__ __forceinline__ void ldmx4(uint32_t* r, uint32_t addr) {
    asm volatile("ldmatrix.sync.aligned.m8n8.x4.shared.b16 {%0,%1,%2,%3}, [%4];"
        : "=r"(r[0]), "=r"(r[1]), "=r"(r[2]), "=r"(r[3]) : "r"(addr));
}
__device__ __forceinline__ void ldmx4t(uint32_t* r, uint32_t addr) {
    asm volatile("ldmatrix.sync.aligned.m8n8.x4.trans.shared.b16 {%0,%1,%2,%3}, [%4];"
        : "=r"(r[0]), "=r"(r[1]), "=r"(r[2]), "=r"(r[3]) : "r"(addr));
}
__device__ __forceinline__ void mma16816(float* d, const uint32_t* a, const uint32_t* b) {
    asm volatile(
        "mma.sync.aligned.m16n8k16.row.col.f32.bf16.bf16.f32 "
        "{%0,%1,%2,%3}, {%4,%5,%6,%7}, {%8,%9}, {%0,%1,%2,%3};"
        : "+f"(d[0]), "+f"(d[1]), "+f"(d[2]), "+f"(d[3])
        : "r"(a[0]), "r"(a[1]), "r"(a[2]), "r"(a[3]), "r"(b[0]), "r"(b[1]));
}
__device__ __forceinline__ float ex2f(float x) {
    float y;
    asm("ex2.approx.f32 %0, %1;" : "=f"(y) : "f"(x));
    return y;
}
__device__ __forceinline__ uint32_t pack_bf16(float a, float b) {
    __nv_bfloat162 t;
    t.x = __float2bfloat16(a);
    t.y = __float2bfloat16(b);
    return *(uint32_t*)&t;
}
__device__ __forceinline__ void split_pack(float a, float b, uint32_t& h, uint32_t& l) {
    __nv_bfloat16 ha = __float2bfloat16(a), hb = __float2bfloat16(b);
    __nv_bfloat162 th, tl;
    th.x = ha; th.y = hb;
    tl.x = __float2bfloat16(a - __bfloat162float(ha));
    tl.y = __float2bfloat16(b - __bfloat162float(hb));
    h = *(uint32_t*)&th;
    l = *(uint32_t*)&tl;
}

// ---------------- LayerNorm + bf16 split: one block per row ----------------
__global__ __launch_bounds__(256) void ln_split_kernel(
    const float* __restrict__ X, const float* __restrict__ gam,
    const float* __restrict__ bet, __nv_bfloat16* __restrict__ Xh,
    __nv_bfloat16* __restrict__ Xl)
{
    int row = blockIdx.x;
    const float4* x4 = (const float4*)(X + (size_t)row * D_MODEL);
    const float4* g4 = (const float4*)gam;
    const float4* b4 = (const float4*)bet;
    int tid = threadIdx.x;

    float4 v0 = x4[tid];
    float4 v1 = x4[tid + 256];
    float s  = v0.x + v0.y + v0.z + v0.w + v1.x + v1.y + v1.z + v1.w;
    float ss = v0.x*v0.x + v0.y*v0.y + v0.z*v0.z + v0.w*v0.w
             + v1.x*v1.x + v1.y*v1.y + v1.z*v1.z + v1.w*v1.w;

    #pragma unroll
    for (int off = 16; off; off >>= 1) {
        s  += __shfl_xor_sync(0xffffffffu, s,  off);
        ss += __shfl_xor_sync(0xffffffffu, ss, off);
    }
    __shared__ float rs[8], rss[8];
    __shared__ float s_mean, s_rstd;
    int w = tid >> 5, l = tid & 31;
    if (l == 0) { rs[w] = s; rss[w] = ss; }
    __syncthreads();
    if (tid == 0) {
        float t = 0.f, tt = 0.f;
        #pragma unroll
        for (int i = 0; i < 8; i++) { t += rs[i]; tt += rss[i]; }
        float mean = t * (1.f / D_MODEL);
        float var  = tt * (1.f / D_MODEL) - mean * mean;
        s_mean = mean;
        s_rstd = rsqrtf(var + 1e-5f);
    }
    __syncthreads();
    float mean = s_mean, rstd = s_rstd;

    float4 g0 = g4[tid], g1 = g4[tid + 256];
    float4 c0 = b4[tid], c1 = b4[tid + 256];
    float r[8];
    r[0] = (v0.x - mean) * rstd * g0.x + c0.x;
    r[1] = (v0.y - mean) * rstd * g0.y + c0.y;
    r[2] = (v0.z - mean) * rstd * g0.z + c0.z;
    r[3] = (v0.w - mean) * rstd * g0.w + c0.w;
    r[4] = (v1.x - mean) * rstd * g1.x + c1.x;
    r[5] = (v1.y - mean) * rstd * g1.y + c1.y;
    r[6] = (v1.z - mean) * rstd * g1.z + c1.z;
    r[7] = (v1.w - mean) * rstd * g1.w + c1.w;

    uint32_t h0, l0, h1, l1, h2, l2, h3, l3;
    split_pack(r[0], r[1], h0, l0);
    split_pack(r[2], r[3], h1, l1);
    split_pack(r[4], r[5], h2, l2);
    split_pack(r[6], r[7], h3, l3);
    size_t base = (size_t)row * D_MODEL;
    uint2 vh0 = {h0, h1}, vl0 = {l0, l1}, vh1 = {h2, h3}, vl1 = {l2, l3};
    *(uint2*)(Xh + base + tid * 4)         = vh0;
    *(uint2*)(Xh + base + (tid + 256) * 4) = vh1;
    *(uint2*)(Xl + base + tid * 4)         = vl0;
    *(uint2*)(Xl + base + (tid + 256) * 4) = vl1;
}

// ---------------- weight transpose + split: W[K,N] -> Wt_h/Wt_l [N,K] ----------------
__global__ __launch_bounds__(256) void transpose_split_kernel(
    const float* __restrict__ W, __nv_bfloat16* __restrict__ Th,
    __nv_bfloat16* __restrict__ Tl)
{
    __shared__ float t[32][33];
    int bx = blockIdx.x * 32;   // n0
    int by = blockIdx.y * 32;   // k0
    int tx = threadIdx.x & 31, ty = threadIdx.x >> 5;
    #pragma unroll
    for (int r = 0; r < 4; r++)
        t[ty + r * 8][tx] = W[(size_t)(by + ty + r * 8) * D_MODEL + bx + tx];
    __syncthreads();
    #pragma unroll
    for (int r = 0; r < 4; r++) {
        float v = t[tx][ty + r * 8];
        __nv_bfloat16 h = __float2bfloat16(v);
        size_t idx = (size_t)(bx + ty + r * 8) * D_MODEL + by + tx;
        Th[idx] = h;
        Tl[idx] = __float2bfloat16(v - __bfloat162float(h));
    }
}

// ---------------- HMMA bf16x3 GEMM: 128x128 tile, BK=64, 3 passes ----------------
// SPLIT=0: write fp32 C (+bias). SPLIT=1: write bf16 hi/lo Ch/Cl (+bias).
#define GDEPTH 4
#define STAGE_BYTES 32768
#define GEMM_SMEM (GDEPTH * STAGE_BYTES)
#define NKITER 32
#define NITER  (3 * NKITER)

template <int SPLIT>
__global__ __launch_bounds__(256) void gemm_hmma(
    const __nv_bfloat16* __restrict__ Ah, const __nv_bfloat16* __restrict__ Al,
    const __nv_bfloat16* __restrict__ Bh, const __nv_bfloat16* __restrict__ Bl,
    const float* __restrict__ bias, float* __restrict__ C,
    __nv_bfloat16* __restrict__ Ch, __nv_bfloat16* __restrict__ Cl)
{
    extern __shared__ __align__(1024) char smc[];
    uint32_t sbase = smem_u32(smc);
    int tid  = threadIdx.x;
    int wid  = tid >> 5;
    int lane = tid & 31;

    int bx = blockIdx.x * 128;   // N
    int by = blockIdx.y * 128;   // M
    int wm = wid & 1;
    int wn = wid >> 1;

    const __nv_bfloat16* Asrc[3] = {Ah, Al, Ah};
    const __nv_bfloat16* Bsrc[3] = {Bh, Bh, Bl};

    float acc[4][4][4];
    #pragma unroll
    for (int i = 0; i < 4; i++)
        #pragma unroll
        for (int j = 0; j < 4; j++)
            #pragma unroll
            for (int k = 0; k < 4; k++) acc[i][j][k] = 0.f;

    int lr = lane & 7, g = lane >> 3;
    int a_row = wm * 64 + ((g & 1) << 3) + lr;
    int a_col = (g >> 1) << 4;
    int b_row = wn * 32 + ((g >> 1) << 3) + lr;
    int b_col = (g & 1) << 4;

    auto issue = [&](int it) {
        int p  = it >> 5;
        int k0 = (it & (NKITER - 1)) * 64;
        int s  = it & (GDEPTH - 1);
        uint32_t sa = sbase + s * STAGE_BYTES;
        uint32_t sb = sa + 16384;
        const __nv_bfloat16* Ap = Asrc[p];
        const __nv_bfloat16* Bp = Bsrc[p];
        #pragma unroll
        for (int j = 0; j < 4; j++) {
            int c = tid + j * 256;
            int r = c >> 3, c16 = c & 7;
            uint32_t off = SWZ128((uint32_t)(r * 128 + c16 * 16));
            cp_async16(sa + off, Ap + (size_t)(by + r) * D_MODEL + k0 + c16 * 8);
            cp_async16(sb + off, Bp + (size_t)(bx + r) * D_MODEL + k0 + c16 * 8);
        }
        CP_COMMIT();
    };

    issue(0); issue(1); issue(2);

    for (int i = 0; i < NITER; i++) {
        if (i + 3 < NITER) issue(i + 3); else CP_COMMIT();
        CP_WAIT3();
        __syncthreads();

        int s = i & (GDEPTH - 1);
        uint32_t sa = sbase + s * STAGE_BYTES;
        uint32_t sb = sa + 16384;

        #pragma unroll
        for (int ks = 0; ks < 4; ks++) {
            uint32_t afr[4][4], bfr[2][4];
            #pragma unroll
            for (int mt = 0; mt < 4; mt++)
                ldmx4(afr[mt], sa + SWZ128((uint32_t)((a_row + mt * 16) * 128 + ks * 32 + a_col)));
            #pragma unroll
            for (int nt = 0; nt < 2; nt++)
                ldmx4(bfr[nt], sb + SWZ128((uint32_t)((b_row + nt * 16) * 128 + ks * 32 + b_col)));
            #pragma unroll
            for (int mt = 0; mt < 4; mt++) {
                #pragma unroll
                for (int nt = 0; nt < 2; nt++) {
                    mma16816(acc[mt][nt * 2],     afr[mt], bfr[nt]);
                    mma16816(acc[mt][nt * 2 + 1], afr[mt], bfr[nt] + 2);
                }
            }
        }
        __syncthreads();
    }

    int qrow = lane >> 2;
    int qcol = (lane & 3) * 2;
    #pragma unroll
    for (int mt = 0; mt < 4; mt++) {
        int m0 = by + wm * 64 + mt * 16 + qrow;
        #pragma unroll
        for (int ntt = 0; ntt < 4; ntt++) {
            int n = bx + wn * 32 + ntt * 8 + qcol;
            float2 bv = *(const float2*)&bias[n];
            float x0 = acc[mt][ntt][0] + bv.x;
            float x1 = acc[mt][ntt][1] + bv.y;
            float x2 = acc[mt][ntt][2] + bv.x;
            float x3 = acc[mt][ntt][3] + bv.y;
            if (SPLIT) {
                uint32_t h0, l0, h1, l1;
                split_pack(x0, x1, h0, l0);
                split_pack(x2, x3, h1, l1);
                *(uint32_t*)&Ch[(size_t)m0 * D_MODEL + n]       = h0;
                *(uint32_t*)&Cl[(size_t)m0 * D_MODEL + n]       = l0;
                *(uint32_t*)&Ch[(size_t)(m0 + 8) * D_MODEL + n] = h1;
                *(uint32_t*)&Cl[(size_t)(m0 + 8) * D_MODEL + n] = l1;
            } else {
                float2 r0 = {x0, x1}, r1 = {x2, x3};
                *(float2*)&C[(size_t)m0 * D_MODEL + n]       = r0;
                *(float2*)&C[(size_t)(m0 + 8) * D_MODEL + n] = r1;
            }
        }
    }
}

// ---------------- HMMA flash attention (causal, bf16x3 scores + bf16x3 PV) ----------------
// CTA: 128 q-rows x 1 head. 256 threads = 8 warps, each owns 16 q-rows.
// K-tile = 64 keys, double-buffered cp.async.
// smem: Qh,Ql 32KB each; 2 stages x (Kh,Kl,Vh,Vl 16KB each) = 128KB. Total 196608.
#define ATT_QH   0
#define ATT_QL   32768
#define ATT_STG  65536
#define ATT_STGB 65536
#define ATT_KH   0
#define ATT_KL   16384
#define ATT_VH   32768
#define ATT_VL   49152
#define ATTN_SMEM 196608
#define KSCALE 0.12751744f   // log2(e)/sqrt(128)

__global__ __launch_bounds__(256, 1) void attn_hmma(
    const __nv_bfloat16* __restrict__ Qh, const __nv_bfloat16* __restrict__ Ql,
    const __nv_bfloat16* __restrict__ Kh, const __nv_bfloat16* __restrict__ Kl,
    const __nv_bfloat16* __restrict__ Vh, const __nv_bfloat16* __restrict__ Vl,
    __nv_bfloat16* __restrict__ AVh, __nv_bfloat16* __restrict__ AVl)
{
    extern __shared__ __align__(1024) char sma[];
    uint32_t sbase = smem_u32(sma);
    int tid  = threadIdx.x;
    int wq   = tid >> 5;
    int lane = tid & 31;

    int qt = (int)gridDim.x - 1 - (int)blockIdx.x;  // long CTAs first
    int bh = blockIdx.y;
    int b  = bh >> 4, h = bh & 15;
    int q0c = qt * 128;
    int ntiles = 2 * qt + 2;

    // ldmatrix address components
    int aq_row = wq * 16 + (lane & 15);                 // Q A-frag row
    int aq_csel = (lane >> 4) << 3;                     // + ks*16
    int bk_row = (lane & 7) + ((lane >> 4) << 3);       // + ntp*16 (K B-frag)
    int bk_csel = ((lane >> 3) & 1) << 3;               // + ks*16
    int v_row = lane & 15;                              // + kk*16 (V trans)
    int v_csel = (lane >> 4) << 3;                      // + n0

    // ---- issue Q (once) ----
    {
        #pragma unroll
        for (int j = 0; j < 8; j++) {
            int idx = tid + j * 256;          // 0..2047
            int r = idx >> 4, c16 = idx & 15;
            uint32_t soff = (uint32_t)((c16 >> 3) * 16384 + SWZ128(r * 128 + (c16 & 7) * 16));
            size_t goff = (size_t)(b * S_LEN + q0c + r) * D_MODEL + h * D_HEAD + c16 * 8;
            cp_async16(sbase + ATT_QH + soff, Qh + goff);
            cp_async16(sbase + ATT_QL + soff, Ql + goff);
        }
        CP_COMMIT();
    }

    auto issueKV = [&](int kt) {
        int k0 = kt * 64;
        uint32_t sg = sbase + ATT_STG + (kt & 1) * ATT_STGB;
        #pragma unroll
        for (int j = 0; j < 4; j++) {
            int idx = tid + j * 256;          // 0..1023
            int r = idx >> 4, c16 = idx & 15;
            uint32_t soff = (uint32_t)((c16 >> 3) * 8192 + SWZ128(r * 128 + (c16 & 7) * 16));
            size_t goff = (size_t)(b * S_LEN + k0 + r) * D_MODEL + h * D_HEAD + c16 * 8;
            cp_async16(sg + ATT_KH + soff, Kh + goff);
            cp_async16(sg + ATT_KL + soff, Kl + goff);
            cp_async16(sg + ATT_VH + soff, Vh + goff);
            cp_async16(sg + ATT_VL + soff, Vl + goff);
        }
        CP_COMMIT();
    };

    issueKV(0);

    float acco[16][4];
    #pragma unroll
    for (int i = 0; i < 16; i++)
        #pragma unroll
        for (int j = 0; j < 4; j++) acco[i][j] = 0.f;
    float m0 = -1e30f, m1 = -1e30f, l0 = 0.f, l1 = 0.f;

    int qrow = lane >> 2;
    int qcol = (lane & 3) << 1;
    int qg0 = q0c + wq * 16 + qrow;   // global q for row half 0 (half1 = +8)

    for (int kt = 0; kt < ntiles; kt++) {
        if (kt + 1 < ntiles) issueKV(kt + 1);
        if (kt + 1 < ntiles) { CP_WAIT1(); } else { CP_WAIT0(); }
        __syncthreads();

        uint32_t sg = sbase + ATT_STG + (kt & 1) * ATT_STGB;
        int k0 = kt * 64;

        // ---- scores: S = Qh*Kh + Ql*Kh + Qh*Kl ----
        float accs[8][4];
        #pragma unroll
        for (int i = 0; i < 8; i++)
            #pragma unroll
            for (int j = 0; j < 4; j++) accs[i][j] = 0.f;

        #pragma unroll
        for (int ks = 0; ks < 8; ks++) {
            int qc = ks * 16 + aq_csel;
            uint32_t qoff = (uint32_t)((qc >> 6) * 16384 + SWZ128(aq_row * 128 + (qc & 63) * 2));
            uint32_t aqh[4], aql[4], bk[4][4];
            ldmx4(aqh, sbase + ATT_QH + qoff);
            ldmx4(aql, sbase + ATT_QL + qoff);
            int kc = ks * 16 + bk_csel;
            uint32_t kcoff = (uint32_t)((kc >> 6) * 8192);
            #pragma unroll
            for (int ntp = 0; ntp < 4; ntp++)
                ldmx4(bk[ntp], sg + ATT_KH + kcoff + SWZ128((ntp * 16 + bk_row) * 128 + (kc & 63) * 2));
            #pragma unroll
            for (int ntp = 0; ntp < 4; ntp++) {
                mma16816(accs[ntp * 2],     aqh, bk[ntp]);
                mma16816(accs[ntp * 2 + 1], aqh, bk[ntp] + 2);
                mma16816(accs[ntp * 2],     aql, bk[ntp]);
                mma16816(accs[ntp * 2 + 1], aql, bk[ntp] + 2);
            }
            #pragma unroll
            for (int ntp = 0; ntp < 4; ntp++)
                ldmx4(bk[ntp], sg + ATT_KL + kcoff + SWZ128((ntp * 16 + bk_row) * 128 + (kc & 63) * 2));
            #pragma unroll
            for (int ntp = 0; ntp < 4; ntp++) {
                mma16816(accs[ntp * 2],     aqh, bk[ntp]);
                mma16816(accs[ntp * 2 + 1], aqh, bk[ntp] + 2);
            }
        }

        // ---- scale (+ causal mask on diagonal tiles) ----
        bool masked = (k0 + 63 > q0c);
        #pragma unroll
        for (int nt = 0; nt < 8; nt++) {
            #pragma unroll
            for (int j = 0; j < 4; j++) accs[nt][j] *= KSCALE;
            if (masked) {
                int kg = k0 + nt * 8 + qcol;
                if (kg     > qg0)     accs[nt][0] = -3e38f;
                if (kg + 1 > qg0)     accs[nt][1] = -3e38f;
                if (kg     > qg0 + 8) accs[nt][2] = -3e38f;
                if (kg + 1 > qg0 + 8) accs[nt][3] = -3e38f;
            }
        }

        // ---- online softmax (log2 domain) ----
        float t0 = -3e38f, t1 = -3e38f;
        #pragma unroll
        for (int nt = 0; nt < 8; nt++) {
            t0 = fmaxf(t0, fmaxf(accs[nt][0], accs[nt][1]));
            t1 = fmaxf(t1, fmaxf(accs[nt][2], accs[nt][3]));
        }
        t0 = fmaxf(t0, __shfl_xor_sync(0xffffffffu, t0, 1));
        t0 = fmaxf(t0, __shfl_xor_sync(0xffffffffu, t0, 2));
        t1 = fmaxf(t1, __shfl_xor_sync(0xffffffffu, t1, 1));
        t1 = fmaxf(t1, __shfl_xor_sync(0xffffffffu, t1, 2));
        float mn0 = fmaxf(m0, t0), mn1 = fmaxf(m1, t1);
        float c0 = ex2f(m0 - mn0), c1 = ex2f(m1 - mn1);
        m0 = mn0; m1 = mn1;

        float s0 = 0.f, s1 = 0.f;
        #pragma unroll
        for (int nt = 0; nt < 8; nt++) {
            accs[nt][0] = ex2f(accs[nt][0] - mn0);
            accs[nt][1] = ex2f(accs[nt][1] - mn0);
            accs[nt][2] = ex2f(accs[nt][2] - mn1);
            accs[nt][3] = ex2f(accs[nt][3] - mn1);
            s0 += accs[nt][0] + accs[nt][1];
            s1 += accs[nt][2] + accs[nt][3];
        }
        s0 += __shfl_xor_sync(0xffffffffu, s0, 1);
        s0 += __shfl_xor_sync(0xffffffffu, s0, 2);
        s1 += __shfl_xor_sync(0xffffffffu, s1, 1);
        s1 += __shfl_xor_sync(0xffffffffu, s1, 2);
        l0 = l0 * c0 + s0;
        l1 = l1 * c1 + s1;

        #pragma unroll
        for (int nt = 0; nt < 16; nt++) {
            acco[nt][0] *= c0; acco[nt][1] *= c0;
            acco[nt][2] *= c1; acco[nt][3] *= c1;
        }

        // ---- PV: O += Ph*Vh + Pl*Vh + Ph*Vl ----
        #pragma unroll
        for (int kk = 0; kk < 4; kk++) {
            uint32_t ph[4], pl[4];
            split_pack(accs[2*kk][0],   accs[2*kk][1],   ph[0], pl[0]);
            split_pack(accs[2*kk][2],   accs[2*kk][3],   ph[1], pl[1]);
            split_pack(accs[2*kk+1][0], accs[2*kk+1][1], ph[2], pl[2]);
            split_pack(accs[2*kk+1][2], accs[2*kk+1][3], ph[3], pl[3]);
            int vr = kk * 16 + v_row;
            #pragma unroll
            for (int np = 0; np < 8; np++) {
                int n0 = np * 16 + v_csel;
                uint32_t voff = (uint32_t)((n0 >> 6) * 8192 + SWZ128(vr * 128 + (n0 & 63) * 2));
                uint32_t vf[4];
                ldmx4t(vf, sg + ATT_VH + voff);
                mma16816(acco[np * 2],     ph, vf);
                mma16816(acco[np * 2 + 1], ph, vf + 2);
                mma16816(acco[np * 2],     pl, vf);
                mma16816(acco[np * 2 + 1], pl, vf + 2);
            }
            #pragma unroll
            for (int np = 0; np < 8; np++) {
                int n0 = np * 16 + v_csel;
                uint32_t voff = (uint32_t)((n0 >> 6) * 8192 + SWZ128(vr * 128 + (n0 & 63) * 2));
                uint32_t vf[4];
                ldmx4t(vf, sg + ATT_VL + voff);
                mma16816(acco[np * 2],     ph, vf);
                mma16816(acco[np * 2 + 1], ph, vf + 2);
            }
        }
        __syncthreads();
    }

    // ---- epilogue: normalize, split, store ----
    float inv0 = 1.f / l0, inv1 = 1.f / l1;
    size_t row0 = (size_t)(b * S_LEN + qg0) * D_MODEL + h * D_HEAD;
    size_t row1 = row0 + 8 * D_MODEL;
    #pragma unroll
    for (int nt = 0; nt < 16; nt++) {
        int n = nt * 8 + qcol;
        uint32_t h0, lo0, h1, lo1;
        split_pack(acco[nt][0] * inv0, acco[nt][1] * inv0, h0, lo0);
        split_pack(acco[nt][2] * inv1, acco[nt][3] * inv1, h1, lo1);
        *(uint32_t*)&AVh[row0 + n] = h0;
        *(uint32_t*)&AVl[row0 + n] = lo0;
        *(uint32_t*)&AVh[row1 + n] = h1;
        *(uint32_t*)&AVl[row1 + n] = lo1;
    }
}

// ---------------- launch ----------------
extern "C" void kernel_launch(void* const* d_in, const int* in_sizes, int n_in,
                              void* d_out, int out_size)
{
    const float* X    = (const float*)d_in[0];
    const float* ln_g = (const float*)d_in[1];
    const float* ln_b = (const float*)d_in[2];
    const float* Wq   = (const float*)d_in[3];
    const float* bq   = (const float*)d_in[4];
    const float* Wk   = (const float*)d_in[5];
    const float* bk   = (const float*)d_in[6];
    const float* Wv   = (const float*)d_in[7];
    const float* bv   = (const float*)d_in[8];
    const float* Wo   = (const float*)d_in[9];
    const float* bo   = (const float*)d_in[10];
    float* out = (float*)d_out;

    __nv_bfloat16 *Xh, *Xl, *Qh, *Ql, *Kh, *Kl, *Vh, *Vl, *AVh, *AVl, *Wth, *Wtl;
    cudaGetSymbolAddress((void**)&Xh,  g_Xh);
    cudaGetSymbolAddress((void**)&Xl,  g_Xl);
    cudaGetSymbolAddress((void**)&Qh,  g_Qh);
    cudaGetSymbolAddress((void**)&Ql,  g_Ql);
    cudaGetSymbolAddress((void**)&Kh,  g_Kh);
    cudaGetSymbolAddress((void**)&Kl,  g_Kl);
    cudaGetSymbolAddress((void**)&Vh,  g_Vh);
    cudaGetSymbolAddress((void**)&Vl,  g_Vl);
    cudaGetSymbolAddress((void**)&AVh, g_AVh);
    cudaGetSymbolAddress((void**)&AVl, g_AVl);
    cudaGetSymbolAddress((void**)&Wth, g_Wth);
    cudaGetSymbolAddress((void**)&Wtl, g_Wtl);

    const size_t WSZ = (size_t)D_MODEL * D_MODEL;

    dim3 tg(D_MODEL / 32, D_MODEL / 32);
    transpose_split_kernel<<<tg, 256>>>(Wq, Wth + 0 * WSZ, Wtl + 0 * WSZ);
    transpose_split_kernel<<<tg, 256>>>(Wk, Wth + 1 * WSZ, Wtl + 1 * WSZ);
    transpose_split_kernel<<<tg, 256>>>(Wv, Wth + 2 * WSZ, Wtl + 2 * WSZ);
    transpose_split_kernel<<<tg, 256>>>(Wo, Wth + 3 * WSZ, Wtl + 3 * WSZ);

    ln_split_kernel<<<NROWS, 256>>>(X, ln_g, ln_b, Xh, Xl);

    cudaFuncSetAttribute(gemm_hmma<0>, cudaFuncAttributeMaxDynamicSharedMemorySize, GEMM_SMEM);
    cudaFuncSetAttribute(gemm_hmma<1>, cudaFuncAttributeMaxDynamicSharedMemorySize, GEMM_SMEM);
    dim3 gg(D_MODEL / 128, NROWS / 128);
    gemm_hmma<1><<<gg, 256, GEMM_SMEM>>>(Xh, Xl, Wth + 0 * WSZ, Wtl + 0 * WSZ, bq, nullptr, Qh, Ql);
    gemm_hmma<1><<<gg, 256, GEMM_SMEM>>>(Xh, Xl, Wth + 1 * WSZ, Wtl + 1 * WSZ, bk, nullptr, Kh, Kl);
    gemm_hmma<1><<<gg, 256, GEMM_SMEM>>>(Xh, Xl, Wth + 2 * WSZ, Wtl + 2 * WSZ, bv, nullptr, Vh, Vl);

    cudaFuncSetAttribute(attn_hmma, cudaFuncAttributeMaxDynamicSharedMemorySize, ATTN_SMEM);
    attn_hmma<<<dim3(S_LEN / 128, BATCH * N_HEADS), 256, ATTN_SMEM>>>(
        Qh, Ql, Kh, Kl, Vh, Vl, AVh, AVl);

    gemm_hmma<0><<<gg, 256, GEMM_SMEM>>>(AVh, AVl, Wth + 3 * WSZ, Wtl + 3 * WSZ, bo, out, nullptr, nullptr);
}

// round 10
// speedup vs baseline: 4.7382x; 1.7394x over previous
#include <cuda_runtime.h>
#include <cuda_bf16.h>
#include <math.h>
#include <cstdint>

#define D_MODEL 2048
#define S_LEN   2048
#define BATCH   2
#define NROWS   (BATCH * S_LEN)   // 4096
#define N_HEADS 16
#define D_HEAD  128

// ---------------- scratch (alloc-free rule: __device__ globals) ----------------
__device__ __nv_bfloat16 g_Xh [(size_t)NROWS * D_MODEL];
__device__ __nv_bfloat16 g_Xl [(size_t)NROWS * D_MODEL];
__device__ __nv_bfloat16 g_Qh [(size_t)NROWS * D_MODEL];
__device__ __nv_bfloat16 g_Ql [(size_t)NROWS * D_MODEL];
__device__ __nv_bfloat16 g_Kh [(size_t)NROWS * D_MODEL];
__device__ __nv_bfloat16 g_Kl [(size_t)NROWS * D_MODEL];
__device__ __nv_bfloat16 g_Vh [(size_t)NROWS * D_MODEL];
__device__ __nv_bfloat16 g_Vl [(size_t)NROWS * D_MODEL];
__device__ __nv_bfloat16 g_AVh[(size_t)NROWS * D_MODEL];
__device__ __nv_bfloat16 g_AVl[(size_t)NROWS * D_MODEL];
// transposed weight splits: [4][N=2048][K=2048], order: Wq, Wk, Wv, Wo
__device__ __nv_bfloat16 g_Wth[(size_t)4 * D_MODEL * D_MODEL];
__device__ __nv_bfloat16 g_Wtl[(size_t)4 * D_MODEL * D_MODEL];

// ---------------- PTX helpers (valid on plain sm_103 target) ----------------
__device__ __forceinline__ uint32_t smem_u32(const void* p) {
    uint32_t a;
    asm("{ .reg .u64 t; cvta.to.shared.u64 t, %1; cvt.u32.u64 %0, t; }" : "=r"(a) : "l"(p));
    return a;
}
#define SWZ128(off) ((off) ^ (((off) >> 3) & 0x70))

__device__ __forceinline__ void cp_async16(uint32_t saddr, const void* gaddr) {
    asm volatile("cp.async.cg.shared.global [%0], [%1], 16;\n" :: "r"(saddr), "l"(gaddr));
}
#define CP_COMMIT() asm volatile("cp.async.commit_group;\n" ::: "memory")
#define CP_WAIT0()  asm volatile("cp.async.wait_group 0;\n" ::: "memory")
#define CP_WAIT1()  asm volatile("cp.async.wait_group 1;\n" ::: "memory")
#define CP_WAIT2()  asm volatile("cp.async.wait_group 2;\n" ::: "memory")

__device__ __forceinline__ void ldmx4(uint32_t* r, uint32_t addr) {
    asm volatile("ldmatrix.sync.aligned.m8n8.x4.shared.b16 {%0,%1,%2,%3}, [%4];"
        : "=r"(r[0]), "=r"(r[1]), "=r"(r[2]), "=r"(r[3]) : "r"(addr));
}
__device__ __forceinline__ void ldmx4t(uint32_t* r, uint32_t addr) {
    asm volatile("ldmatrix.sync.aligned.m8n8.x4.trans.shared.b16 {%0,%1,%2,%3}, [%4];"
        : "=r"(r[0]), "=r"(r[1]), "=r"(r[2]), "=r"(r[3]) : "r"(addr));
}
__device__ __forceinline__ void mma16816(float* d, const uint32_t* a, const uint32_t* b) {
    asm volatile(
        "mma.sync.aligned.m16n8k16.row.col.f32.bf16.bf16.f32 "
        "{%0,%1,%2,%3}, {%4,%5,%6,%7}, {%8,%9}, {%0,%1,%2,%3};"
        : "+f"(d[0]), "+f"(d[1]), "+f"(d[2]), "+f"(d[3])
        : "r"(a[0]), "r"(a[1]), "r"(a[2]), "r"(a[3]), "r"(b[0]), "r"(b[1]));
}
__device__ __forceinline__ float ex2f(float x) {
    float y;
    asm("ex2.approx.f32 %0, %1;" : "=f"(y) : "f"(x));
    return y;
}
__device__ __forceinline__ void split_pack(float a, float b, uint32_t& h, uint32_t& l) {
    __nv_bfloat16 ha = __float2bfloat16(a), hb = __float2bfloat16(b);
    __nv_bfloat162 th, tl;
    th.x = ha; th.y = hb;
    tl.x = __float2bfloat16(a - __bfloat162float(ha));
    tl.y = __float2bfloat16(b - __bfloat162float(hb));
    h = *(uint32_t*)&th;
    l = *(uint32_t*)&tl;
}

// ---------------- LayerNorm + bf16 split: one block per row ----------------
__global__ __launch_bounds__(256) void ln_split_kernel(
    const float* __restrict__ X, const float* __restrict__ gam,
    const float* __restrict__ bet, __nv_bfloat16* __restrict__ Xh,
    __nv_bfloat16* __restrict__ Xl)
{
    int row = blockIdx.x;
    const float4* x4 = (const float4*)(X + (size_t)row * D_MODEL);
    const float4* g4 = (const float4*)gam;
    const float4* b4 = (const float4*)bet;
    int tid = threadIdx.x;

    float4 v0 = x4[tid];
    float4 v1 = x4[tid + 256];
    float s  = v0.x + v0.y + v0.z + v0.w + v1.x + v1.y + v1.z + v1.w;
    float ss = v0.x*v0.x + v0.y*v0.y + v0.z*v0.z + v0.w*v0.w
             + v1.x*v1.x + v1.y*v1.y + v1.z*v1.z + v1.w*v1.w;

    #pragma unroll
    for (int off = 16; off; off >>= 1) {
        s  += __shfl_xor_sync(0xffffffffu, s,  off);
        ss += __shfl_xor_sync(0xffffffffu, ss, off);
    }
    __shared__ float rs[8], rss[8];
    __shared__ float s_mean, s_rstd;
    int w = tid >> 5, l = tid & 31;
    if (l == 0) { rs[w] = s; rss[w] = ss; }
    __syncthreads();
    if (tid == 0) {
        float t = 0.f, tt = 0.f;
        #pragma unroll
        for (int i = 0; i < 8; i++) { t += rs[i]; tt += rss[i]; }
        float mean = t * (1.f / D_MODEL);
        float var  = tt * (1.f / D_MODEL) - mean * mean;
        s_mean = mean;
        s_rstd = rsqrtf(var + 1e-5f);
    }
    __syncthreads();
    float mean = s_mean, rstd = s_rstd;

    float4 g0 = g4[tid], g1 = g4[tid + 256];
    float4 c0 = b4[tid], c1 = b4[tid + 256];
    float r[8];
    r[0] = (v0.x - mean) * rstd * g0.x + c0.x;
    r[1] = (v0.y - mean) * rstd * g0.y + c0.y;
    r[2] = (v0.z - mean) * rstd * g0.z + c0.z;
    r[3] = (v0.w - mean) * rstd * g0.w + c0.w;
    r[4] = (v1.x - mean) * rstd * g1.x + c1.x;
    r[5] = (v1.y - mean) * rstd * g1.y + c1.y;
    r[6] = (v1.z - mean) * rstd * g1.z + c1.z;
    r[7] = (v1.w - mean) * rstd * g1.w + c1.w;

    uint32_t h0, l0, h1, l1, h2, l2, h3, l3;
    split_pack(r[0], r[1], h0, l0);
    split_pack(r[2], r[3], h1, l1);
    split_pack(r[4], r[5], h2, l2);
    split_pack(r[6], r[7], h3, l3);
    size_t base = (size_t)row * D_MODEL;
    uint2 vh0 = {h0, h1}, vl0 = {l0, l1}, vh1 = {h2, h3}, vl1 = {l2, l3};
    *(uint2*)(Xh + base + tid * 4)         = vh0;
    *(uint2*)(Xh + base + (tid + 256) * 4) = vh1;
    *(uint2*)(Xl + base + tid * 4)         = vl0;
    *(uint2*)(Xl + base + (tid + 256) * 4) = vl1;
}

// ---------------- weight transpose + split (all 4 weights, grid.z selects) ----------------
__global__ __launch_bounds__(256) void transpose_split_kernel(
    const float* __restrict__ W0, const float* __restrict__ W1,
    const float* __restrict__ W2, const float* __restrict__ W3,
    __nv_bfloat16* __restrict__ Th, __nv_bfloat16* __restrict__ Tl)
{
    __shared__ float t[32][33];
    int wsel = blockIdx.z;
    const float* W = (wsel == 0) ? W0 : (wsel == 1) ? W1 : (wsel == 2) ? W2 : W3;
    size_t obase = (size_t)wsel * D_MODEL * D_MODEL;
    int bx = blockIdx.x * 32;   // n0
    int by = blockIdx.y * 32;   // k0
    int tx = threadIdx.x & 31, ty = threadIdx.x >> 5;
    #pragma unroll
    for (int r = 0; r < 4; r++)
        t[ty + r * 8][tx] = W[(size_t)(by + ty + r * 8) * D_MODEL + bx + tx];
    __syncthreads();
    #pragma unroll
    for (int r = 0; r < 4; r++) {
        float v = t[tx][ty + r * 8];
        __nv_bfloat16 h = __float2bfloat16(v);
        size_t idx = obase + (size_t)(bx + ty + r * 8) * D_MODEL + by + tx;
        Th[idx] = h;
        Tl[idx] = __float2bfloat16(v - __bfloat162float(h));
    }
}

// ---------------- HMMA bf16x3 GEMM, SINGLE K-PASS ----------------
// Per k-chunk (BK=64) stage holds Ah|Al|Bh|Bl (16KB each = 64KB). 3-stage pipeline.
// All three products (AhBh + AlBh + AhBl) issued per fragment load.
#define TILE_B 16384
#define GDEPTH 3
#define STAGE_BYTES (4 * TILE_B)       // 64KB
#define GEMM_SMEM (GDEPTH * STAGE_BYTES)  // 192KB
#define NKITER 32

template <int SPLIT>
__global__ __launch_bounds__(256) void gemm_hmma(
    const __nv_bfloat16* __restrict__ Ah, const __nv_bfloat16* __restrict__ Al,
    const __nv_bfloat16* __restrict__ Bh, const __nv_bfloat16* __restrict__ Bl,
    const float* __restrict__ bias, float* __restrict__ C,
    __nv_bfloat16* __restrict__ Ch, __nv_bfloat16* __restrict__ Cl)
{
    extern __shared__ __align__(1024) char smc[];
    uint32_t sbase = smem_u32(smc);
    int tid  = threadIdx.x;
    int wid  = tid >> 5;
    int lane = tid & 31;

    int bx = blockIdx.x * 128;   // N
    int by = blockIdx.y * 128;   // M
    int wm = wid & 1;
    int wn = wid >> 1;

    float acc[4][4][4];
    #pragma unroll
    for (int i = 0; i < 4; i++)
        #pragma unroll
        for (int j = 0; j < 4; j++)
            #pragma unroll
            for (int k = 0; k < 4; k++) acc[i][j][k] = 0.f;

    int lr = lane & 7, g = lane >> 3;
    int a_row = wm * 64 + ((g & 1) << 3) + lr;
    int a_col = (g >> 1) << 4;
    int b_row = wn * 32 + ((g >> 1) << 3) + lr;
    int b_col = (g & 1) << 4;

    auto issue = [&](int it) {
        int k0 = it * 64;
        int s  = it % GDEPTH;
        uint32_t sa = sbase + s * STAGE_BYTES;
        #pragma unroll
        for (int j = 0; j < 4; j++) {
            int c = tid + j * 256;            // 0..1023
            int r = c >> 3, c16 = c & 7;
            uint32_t off = SWZ128((uint32_t)(r * 128 + c16 * 16));
            size_t aoff = (size_t)(by + r) * D_MODEL + k0 + c16 * 8;
            size_t boff = (size_t)(bx + r) * D_MODEL + k0 + c16 * 8;
            cp_async16(sa + off,                 Ah + aoff);
            cp_async16(sa + TILE_B + off,        Al + aoff);
            cp_async16(sa + 2 * TILE_B + off,    Bh + boff);
            cp_async16(sa + 3 * TILE_B + off,    Bl + boff);
        }
        CP_COMMIT();
    };

    issue(0); issue(1);

    for (int i = 0; i < NKITER; i++) {
        if (i + 2 < NKITER) issue(i + 2); else CP_COMMIT();
        CP_WAIT2();
        __syncthreads();

        int s = i % GDEPTH;
        uint32_t sa = sbase + s * STAGE_BYTES;

        #pragma unroll
        for (int ks = 0; ks < 4; ks++) {
            uint32_t ahf[4][4], alf[4][4], bhf[2][4], blf[2][4];
            #pragma unroll
            for (int mt = 0; mt < 4; mt++) {
                uint32_t off = SWZ128((uint32_t)((a_row + mt * 16) * 128 + ks * 32 + a_col));
                ldmx4(ahf[mt], sa + off);
                ldmx4(alf[mt], sa + TILE_B + off);
            }
            #pragma unroll
            for (int nt = 0; nt < 2; nt++) {
                uint32_t off = SWZ128((uint32_t)((b_row + nt * 16) * 128 + ks * 32 + b_col));
                ldmx4(bhf[nt], sa + 2 * TILE_B + off);
                ldmx4(blf[nt], sa + 3 * TILE_B + off);
            }
            #pragma unroll
            for (int mt = 0; mt < 4; mt++) {
                #pragma unroll
                for (int nt = 0; nt < 2; nt++) {
                    mma16816(acc[mt][nt * 2],     ahf[mt], bhf[nt]);
                    mma16816(acc[mt][nt * 2 + 1], ahf[mt], bhf[nt] + 2);
                    mma16816(acc[mt][nt * 2],     alf[mt], bhf[nt]);
                    mma16816(acc[mt][nt * 2 + 1], alf[mt], bhf[nt] + 2);
                    mma16816(acc[mt][nt * 2],     ahf[mt], blf[nt]);
                    mma16816(acc[mt][nt * 2 + 1], ahf[mt], blf[nt] + 2);
                }
            }
        }
        __syncthreads();
    }

    int qrow = lane >> 2;
    int qcol = (lane & 3) * 2;
    #pragma unroll
    for (int mt = 0; mt < 4; mt++) {
        int m0 = by + wm * 64 + mt * 16 + qrow;
        #pragma unroll
        for (int ntt = 0; ntt < 4; ntt++) {
            int n = bx + wn * 32 + ntt * 8 + qcol;
            float2 bv = *(const float2*)&bias[n];
            float x0 = acc[mt][ntt][0] + bv.x;
            float x1 = acc[mt][ntt][1] + bv.y;
            float x2 = acc[mt][ntt][2] + bv.x;
            float x3 = acc[mt][ntt][3] + bv.y;
            if (SPLIT) {
                uint32_t h0, l0, h1, l1;
                split_pack(x0, x1, h0, l0);
                split_pack(x2, x3, h1, l1);
                *(uint32_t*)&Ch[(size_t)m0 * D_MODEL + n]       = h0;
                *(uint32_t*)&Cl[(size_t)m0 * D_MODEL + n]       = l0;
                *(uint32_t*)&Ch[(size_t)(m0 + 8) * D_MODEL + n] = h1;
                *(uint32_t*)&Cl[(size_t)(m0 + 8) * D_MODEL + n] = l1;
            } else {
                float2 r0 = {x0, x1}, r1 = {x2, x3};
                *(float2*)&C[(size_t)m0 * D_MODEL + n]       = r0;
                *(float2*)&C[(size_t)(m0 + 8) * D_MODEL + n] = r1;
            }
        }
    }
}

// ---------------- HMMA flash attention (causal, bf16x3 scores + bf16x3 PV) ----------------
#define ATT_QH   0
#define ATT_QL   32768
#define ATT_STG  65536
#define ATT_STGB 65536
#define ATT_KH   0
#define ATT_KL   16384
#define ATT_VH   32768
#define ATT_VL   49152
#define ATTN_SMEM 196608
#define KSCALE 0.12751744f   // log2(e)/sqrt(128)

__global__ __launch_bounds__(256, 1) void attn_hmma(
    const __nv_bfloat16* __restrict__ Qh, const __nv_bfloat16* __restrict__ Ql,
    const __nv_bfloat16* __restrict__ Kh, const __nv_bfloat16* __restrict__ Kl,
    const __nv_bfloat16* __restrict__ Vh, const __nv_bfloat16* __restrict__ Vl,
    __nv_bfloat16* __restrict__ AVh, __nv_bfloat16* __restrict__ AVl)
{
    extern __shared__ __align__(1024) char sma[];
    uint32_t sbase = smem_u32(sma);
    int tid  = threadIdx.x;
    int wq   = tid >> 5;
    int lane = tid & 31;

    int qt = (int)gridDim.x - 1 - (int)blockIdx.x;  // long CTAs first
    int bh = blockIdx.y;
    int b  = bh >> 4, h = bh & 15;
    int q0c = qt * 128;
    int ntiles = 2 * qt + 2;

    int aq_row = wq * 16 + (lane & 15);
    int aq_csel = (lane >> 4) << 3;
    int bk_row = (lane & 7) + ((lane >> 4) << 3);
    int bk_csel = ((lane >> 3) & 1) << 3;
    int v_row = lane & 15;
    int v_csel = (lane >> 4) << 3;

    {
        #pragma unroll
        for (int j = 0; j < 8; j++) {
            int idx = tid + j * 256;
            int r = idx >> 4, c16 = idx & 15;
            uint32_t soff = (uint32_t)((c16 >> 3) * 16384 + SWZ128(r * 128 + (c16 & 7) * 16));
            size_t goff = (size_t)(b * S_LEN + q0c + r) * D_MODEL + h * D_HEAD + c16 * 8;
            cp_async16(sbase + ATT_QH + soff, Qh + goff);
            cp_async16(sbase + ATT_QL + soff, Ql + goff);
        }
        CP_COMMIT();
    }

    auto issueKV = [&](int kt) {
        int k0 = kt * 64;
        uint32_t sg = sbase + ATT_STG + (kt & 1) * ATT_STGB;
        #pragma unroll
        for (int j = 0; j < 4; j++) {
            int idx = tid + j * 256;
            int r = idx >> 4, c16 = idx & 15;
            uint32_t soff = (uint32_t)((c16 >> 3) * 8192 + SWZ128(r * 128 + (c16 & 7) * 16));
            size_t goff = (size_t)(b * S_LEN + k0 + r) * D_MODEL + h * D_HEAD + c16 * 8;
            cp_async16(sg + ATT_KH + soff, Kh + goff);
            cp_async16(sg + ATT_KL + soff, Kl + goff);
            cp_async16(sg + ATT_VH + soff, Vh + goff);
            cp_async16(sg + ATT_VL + soff, Vl + goff);
        }
        CP_COMMIT();
    };

    issueKV(0);

    float acco[16][4];
    #pragma unroll
    for (int i = 0; i < 16; i++)
        #pragma unroll
        for (int j = 0; j < 4; j++) acco[i][j] = 0.f;
    float m0 = -1e30f, m1 = -1e30f, l0 = 0.f, l1 = 0.f;

    int qrow = lane >> 2;
    int qcol = (lane & 3) << 1;
    int qg0 = q0c + wq * 16 + qrow;

    for (int kt = 0; kt < ntiles; kt++) {
        if (kt + 1 < ntiles) issueKV(kt + 1);
        if (kt + 1 < ntiles) { CP_WAIT1(); } else { CP_WAIT0(); }
        __syncthreads();

        uint32_t sg = sbase + ATT_STG + (kt & 1) * ATT_STGB;
        int k0 = kt * 64;

        float accs[8][4];
        #pragma unroll
        for (int i = 0; i < 8; i++)
            #pragma unroll
            for (int j = 0; j < 4; j++) accs[i][j] = 0.f;

        #pragma unroll
        for (int ks = 0; ks < 8; ks++) {
            int qc = ks * 16 + aq_csel;
            uint32_t qoff = (uint32_t)((qc >> 6) * 16384 + SWZ128(aq_row * 128 + (qc & 63) * 2));
            uint32_t aqh[4], aql[4], bk[4][4];
            ldmx4(aqh, sbase + ATT_QH + qoff);
            ldmx4(aql, sbase + ATT_QL + qoff);
            int kc = ks * 16 + bk_csel;
            uint32_t kcoff = (uint32_t)((kc >> 6) * 8192);
            #pragma unroll
            for (int ntp = 0; ntp < 4; ntp++)
                ldmx4(bk[ntp], sg + ATT_KH + kcoff + SWZ128((ntp * 16 + bk_row) * 128 + (kc & 63) * 2));
            #pragma unroll
            for (int ntp = 0; ntp < 4; ntp++) {
                mma16816(accs[ntp * 2],     aqh, bk[ntp]);
                mma16816(accs[ntp * 2 + 1], aqh, bk[ntp] + 2);
                mma16816(accs[ntp * 2],     aql, bk[ntp]);
                mma16816(accs[ntp * 2 + 1], aql, bk[ntp] + 2);
            }
            #pragma unroll
            for (int ntp = 0; ntp < 4; ntp++)
                ldmx4(bk[ntp], sg + ATT_KL + kcoff + SWZ128((ntp * 16 + bk_row) * 128 + (kc & 63) * 2));
            #pragma unroll
            for (int ntp = 0; ntp < 4; ntp++) {
                mma16816(accs[ntp * 2],     aqh, bk[ntp]);
                mma16816(accs[ntp * 2 + 1], aqh, bk[ntp] + 2);
            }
        }

        bool masked = (k0 + 63 > q0c);
        #pragma unroll
        for (int nt = 0; nt < 8; nt++) {
            #pragma unroll
            for (int j = 0; j < 4; j++) accs[nt][j] *= KSCALE;
            if (masked) {
                int kg = k0 + nt * 8 + qcol;
                if (kg     > qg0)     accs[nt][0] = -3e38f;
                if (kg + 1 > qg0)     accs[nt][1] = -3e38f;
                if (kg     > qg0 + 8) accs[nt][2] = -3e38f;
                if (kg + 1 > qg0 + 8) accs[nt][3] = -3e38f;
            }
        }

        float t0 = -3e38f, t1 = -3e38f;
        #pragma unroll
        for (int nt = 0; nt < 8; nt++) {
            t0 = fmaxf(t0, fmaxf(accs[nt][0], accs[nt][1]));
            t1 = fmaxf(t1, fmaxf(accs[nt][2], accs[nt][3]));
        }
        t0 = fmaxf(t0, __shfl_xor_sync(0xffffffffu, t0, 1));
        t0 = fmaxf(t0, __shfl_xor_sync(0xffffffffu, t0, 2));
        t1 = fmaxf(t1, __shfl_xor_sync(0xffffffffu, t1, 1));
        t1 = fmaxf(t1, __shfl_xor_sync(0xffffffffu, t1, 2));
        float mn0 = fmaxf(m0, t0), mn1 = fmaxf(m1, t1);
        float c0 = ex2f(m0 - mn0), c1 = ex2f(m1 - mn1);
        m0 = mn0; m1 = mn1;

        float s0 = 0.f, s1 = 0.f;
        #pragma unroll
        for (int nt = 0; nt < 8; nt++) {
            accs[nt][0] = ex2f(accs[nt][0] - mn0);
            accs[nt][1] = ex2f(accs[nt][1] - mn0);
            accs[nt][2] = ex2f(accs[nt][2] - mn1);
            accs[nt][3] = ex2f(accs[nt][3] - mn1);
            s0 += accs[nt][0] + accs[nt][1];
            s1 += accs[nt][2] + accs[nt][3];
        }
        s0 += __shfl_xor_sync(0xffffffffu, s0, 1);
        s0 += __shfl_xor_sync(0xffffffffu, s0, 2);
        s1 += __shfl_xor_sync(0xffffffffu, s1, 1);
        s1 += __shfl_xor_sync(0xffffffffu, s1, 2);
        l0 = l0 * c0 + s0;
        l1 = l1 * c1 + s1;

        #pragma unroll
        for (int nt = 0; nt < 16; nt++) {
            acco[nt][0] *= c0; acco[nt][1] *= c0;
            acco[nt][2] *= c1; acco[nt][3] *= c1;
        }

        #pragma unroll
        for (int kk = 0; kk < 4; kk++) {
            uint32_t ph[4], pl[4];
            split_pack(accs[2*kk][0],   accs[2*kk][1],   ph[0], pl[0]);
            split_pack(accs[2*kk][2],   accs[2*kk][3],   ph[1], pl[1]);
            split_pack(accs[2*kk+1][0], accs[2*kk+1][1], ph[2], pl[2]);
            split_pack(accs[2*kk+1][2], accs[2*kk+1][3], ph[3], pl[3]);
            int vr = kk * 16 + v_row;
            #pragma unroll
            for (int np = 0; np < 8; np++) {
                int n0 = np * 16 + v_csel;
                uint32_t voff = (uint32_t)((n0 >> 6) * 8192 + SWZ128(vr * 128 + (n0 & 63) * 2));
                uint32_t vf[4];
                ldmx4t(vf, sg + ATT_VH + voff);
                mma16816(acco[np * 2],     ph, vf);
                mma16816(acco[np * 2 + 1], ph, vf + 2);
                mma16816(acco[np * 2],     pl, vf);
                mma16816(acco[np * 2 + 1], pl, vf + 2);
            }
            #pragma unroll
            for (int np = 0; np < 8; np++) {
                int n0 = np * 16 + v_csel;
                uint32_t voff = (uint32_t)((n0 >> 6) * 8192 + SWZ128(vr * 128 + (n0 & 63) * 2));
                uint32_t vf[4];
                ldmx4t(vf, sg + ATT_VL + voff);
                mma16816(acco[np * 2],     ph, vf);
                mma16816(acco[np * 2 + 1], ph, vf + 2);
            }
        }
        __syncthreads();
    }

    float inv0 = 1.f / l0, inv1 = 1.f / l1;
    size_t row0 = (size_t)(b * S_LEN + qg0) * D_MODEL + h * D_HEAD;
    size_t row1 = row0 + 8 * D_MODEL;
    #pragma unroll
    for (int nt = 0; nt < 16; nt++) {
        int n = nt * 8 + qcol;
        uint32_t h0, lo0, h1, lo1;
        split_pack(acco[nt][0] * inv0, acco[nt][1] * inv0, h0, lo0);
        split_pack(acco[nt][2] * inv1, acco[nt][3] * inv1, h1, lo1);
        *(uint32_t*)&AVh[row0 + n] = h0;
        *(uint32_t*)&AVl[row0 + n] = lo0;
        *(uint32_t*)&AVh[row1 + n] = h1;
        *(uint32_t*)&AVl[row1 + n] = lo1;
    }
}

// ---------------- launch ----------------
extern "C" void kernel_launch(void* const* d_in, const int* in_sizes, int n_in,
                              void* d_out, int out_size)
{
    const float* X    = (const float*)d_in[0];
    const float* ln_g = (const float*)d_in[1];
    const float* ln_b = (const float*)d_in[2];
    const float* Wq   = (const float*)d_in[3];
    const float* bq   = (const float*)d_in[4];
    const float* Wk   = (const float*)d_in[5];
    const float* bk   = (const float*)d_in[6];
    const float* Wv   = (const float*)d_in[7];
    const float* bv   = (const float*)d_in[8];
    const float* Wo   = (const float*)d_in[9];
    const float* bo   = (const float*)d_in[10];
    float* out = (float*)d_out;

    __nv_bfloat16 *Xh, *Xl, *Qh, *Ql, *Kh, *Kl, *Vh, *Vl, *AVh, *AVl, *Wth, *Wtl;
    cudaGetSymbolAddress((void**)&Xh,  g_Xh);
    cudaGetSymbolAddress((void**)&Xl,  g_Xl);
    cudaGetSymbolAddress((void**)&Qh,  g_Qh);
    cudaGetSymbolAddress((void**)&Ql,  g_Ql);
    cudaGetSymbolAddress((void**)&Kh,  g_Kh);
    cudaGetSymbolAddress((void**)&Kl,  g_Kl);
    cudaGetSymbolAddress((void**)&Vh,  g_Vh);
    cudaGetSymbolAddress((void**)&Vl,  g_Vl);
    cudaGetSymbolAddress((void**)&AVh, g_AVh);
    cudaGetSymbolAddress((void**)&AVl, g_AVl);
    cudaGetSymbolAddress((void**)&Wth, g_Wth);
    cudaGetSymbolAddress((void**)&Wtl, g_Wtl);

    const size_t WSZ = (size_t)D_MODEL * D_MODEL;

    dim3 tg(D_MODEL / 32, D_MODEL / 32, 4);
    transpose_split_kernel<<<tg, 256>>>(Wq, Wk, Wv, Wo, Wth, Wtl);

    ln_split_kernel<<<NROWS, 256>>>(X, ln_g, ln_b, Xh, Xl);

    cudaFuncSetAttribute(gemm_hmma<0>, cudaFuncAttributeMaxDynamicSharedMemorySize, GEMM_SMEM);
    cudaFuncSetAttribute(gemm_hmma<1>, cudaFuncAttributeMaxDynamicSharedMemorySize, GEMM_SMEM);
    dim3 gg(D_MODEL / 128, NROWS / 128);
    gemm_hmma<1><<<gg, 256, GEMM_SMEM>>>(Xh, Xl, Wth + 0 * WSZ, Wtl + 0 * WSZ, bq, nullptr, Qh, Ql);
    gemm_hmma<1><<<gg, 256, GEMM_SMEM>>>(Xh, Xl, Wth + 1 * WSZ, Wtl + 1 * WSZ, bk, nullptr, Kh, Kl);
    gemm_hmma<1><<<gg, 256, GEMM_SMEM>>>(Xh, Xl, Wth + 2 * WSZ, Wtl + 2 * WSZ, bv, nullptr, Vh, Vl);

    cudaFuncSetAttribute(attn_hmma, cudaFuncAttributeMaxDynamicSharedMemorySize, ATTN_SMEM);
    attn_hmma<<<dim3(S_LEN / 128, BATCH * N_HEADS), 256, ATTN_SMEM>>>(
        Qh, Ql, Kh, Kl, Vh, Vl, AVh, AVl);

    gemm_hmma<0><<<gg, 256, GEMM_SMEM>>>(AVh, AVl, Wth + 3 * WSZ, Wtl + 3 * WSZ, bo, out, nullptr, nullptr);
}

// round 13
// speedup vs baseline: 4.9157x; 1.0375x over previous
#include <cuda_runtime.h>
#include <cuda_bf16.h>
#include <math.h>
#include <cstdint>

#define D_MODEL 2048
#define S_LEN   2048
#define BATCH   2
#define NROWS   (BATCH * S_LEN)   // 4096
#define N_HEADS 16
#define D_HEAD  128

// ---------------- scratch (alloc-free rule: __device__ globals) ----------------
__device__ __nv_bfloat16 g_Xh [(size_t)NROWS * D_MODEL];
__device__ __nv_bfloat16 g_Xl [(size_t)NROWS * D_MODEL];
__device__ __nv_bfloat16 g_Qh [(size_t)NROWS * D_MODEL];
__device__ __nv_bfloat16 g_Ql [(size_t)NROWS * D_MODEL];
__device__ __nv_bfloat16 g_Kh [(size_t)NROWS * D_MODEL];
__device__ __nv_bfloat16 g_Kl [(size_t)NROWS * D_MODEL];
__device__ __nv_bfloat16 g_Vh [(size_t)NROWS * D_MODEL];
__device__ __nv_bfloat16 g_Vl [(size_t)NROWS * D_MODEL];
__device__ __nv_bfloat16 g_AVh[(size_t)NROWS * D_MODEL];
__device__ __nv_bfloat16 g_AVl[(size_t)NROWS * D_MODEL];
// transposed weight splits: [4][N=2048][K=2048], order: Wq, Wk, Wv, Wo
__device__ __nv_bfloat16 g_Wth[(size_t)4 * D_MODEL * D_MODEL];
__device__ __nv_bfloat16 g_Wtl[(size_t)4 * D_MODEL * D_MODEL];

// ---------------- PTX helpers (valid on plain sm_103 target) ----------------
__device__ __forceinline__ uint32_t smem_u32(const void* p) {
    uint32_t a;
    asm("{ .reg .u64 t; cvta.to.shared.u64 t, %1; cvt.u32.u64 %0, t; }" : "=r"(a) : "l"(p));
    return a;
}
#define SWZ128(off) ((off) ^ (((off) >> 3) & 0x70))

__device__ __forceinline__ void cp_async16(uint32_t saddr, const void* gaddr) {
    asm volatile("cp.async.cg.shared.global [%0], [%1], 16;\n" :: "r"(saddr), "l"(gaddr));
}
#define CP_COMMIT() asm volatile("cp.async.commit_group;\n" ::: "memory")
#define CP_WAIT0()  asm volatile("cp.async.wait_group 0;\n" ::: "memory")
#define CP_WAIT1()  asm volatile("cp.async.wait_group 1;\n" ::: "memory")
#define CP_WAIT2()  asm volatile("cp.async.wait_group 2;\n" ::: "memory")

__device__ __forceinline__ void ldmx4(uint32_t* r, uint32_t addr) {
    asm volatile("ldmatrix.sync.aligned.m8n8.x4.shared.b16 {%0,%1,%2,%3}, [%4];"
        : "=r"(r[0]), "=r"(r[1]), "=r"(r[2]), "=r"(r[3]) : "r"(addr));
}
__device__ __forceinline__ void ldmx4t(uint32_t* r, uint32_t addr) {
    asm volatile("ldmatrix.sync.aligned.m8n8.x4.trans.shared.b16 {%0,%1,%2,%3}, [%4];"
        : "=r"(r[0]), "=r"(r[1]), "=r"(r[2]), "=r"(r[3]) : "r"(addr));
}
// NOTE: non-volatile — pure register op, lets ptxas interleave independent MMAs.
__device__ __forceinline__ void mma16816(float* d, const uint32_t* a, const uint32_t* b) {
    asm("mma.sync.aligned.m16n8k16.row.col.f32.bf16.bf16.f32 "
        "{%0,%1,%2,%3}, {%4,%5,%6,%7}, {%8,%9}, {%0,%1,%2,%3};"
        : "+f"(d[0]), "+f"(d[1]), "+f"(d[2]), "+f"(d[3])
        : "r"(a[0]), "r"(a[1]), "r"(a[2]), "r"(a[3]), "r"(b[0]), "r"(b[1]));
}
__device__ __forceinline__ float ex2f(float x) {
    float y;
    asm("ex2.approx.f32 %0, %1;" : "=f"(y) : "f"(x));
    return y;
}
__device__ __forceinline__ void split_pack(float a, float b, uint32_t& h, uint32_t& l) {
    __nv_bfloat16 ha = __float2bfloat16(a), hb = __float2bfloat16(b);
    __nv_bfloat162 th, tl;
    th.x = ha; th.y = hb;
    tl.x = __float2bfloat16(a - __bfloat162float(ha));
    tl.y = __float2bfloat16(b - __bfloat162float(hb));
    h = *(uint32_t*)&th;
    l = *(uint32_t*)&tl;
}

// ---------------- LayerNorm + bf16 split: one block per row ----------------
__global__ __launch_bounds__(256) void ln_split_kernel(
    const float* __restrict__ X, const float* __restrict__ gam,
    const float* __restrict__ bet, __nv_bfloat16* __restrict__ Xh,
    __nv_bfloat16* __restrict__ Xl)
{
    int row = blockIdx.x;
    const float4* x4 = (const float4*)(X + (size_t)row * D_MODEL);
    const float4* g4 = (const float4*)gam;
    const float4* b4 = (const float4*)bet;
    int tid = threadIdx.x;

    float4 v0 = x4[tid];
    float4 v1 = x4[tid + 256];
    float s  = v0.x + v0.y + v0.z + v0.w + v1.x + v1.y + v1.z + v1.w;
    float ss = v0.x*v0.x + v0.y*v0.y + v0.z*v0.z + v0.w*v0.w
             + v1.x*v1.x + v1.y*v1.y + v1.z*v1.z + v1.w*v1.w;

    #pragma unroll
    for (int off = 16; off; off >>= 1) {
        s  += __shfl_xor_sync(0xffffffffu, s,  off);
        ss += __shfl_xor_sync(0xffffffffu, ss, off);
    }
    __shared__ float rs[8], rss[8];
    __shared__ float s_mean, s_rstd;
    int w = tid >> 5, l = tid & 31;
    if (l == 0) { rs[w] = s; rss[w] = ss; }
    __syncthreads();
    if (tid == 0) {
        float t = 0.f, tt = 0.f;
        #pragma unroll
        for (int i = 0; i < 8; i++) { t += rs[i]; tt += rss[i]; }
        float mean = t * (1.f / D_MODEL);
        float var  = tt * (1.f / D_MODEL) - mean * mean;
        s_mean = mean;
        s_rstd = rsqrtf(var + 1e-5f);
    }
    __syncthreads();
    float mean = s_mean, rstd = s_rstd;

    float4 g0 = g4[tid], g1 = g4[tid + 256];
    float4 c0 = b4[tid], c1 = b4[tid + 256];
    float r[8];
    r[0] = (v0.x - mean) * rstd * g0.x + c0.x;
    r[1] = (v0.y - mean) * rstd * g0.y + c0.y;
    r[2] = (v0.z - mean) * rstd * g0.z + c0.z;
    r[3] = (v0.w - mean) * rstd * g0.w + c0.w;
    r[4] = (v1.x - mean) * rstd * g1.x + c1.x;
    r[5] = (v1.y - mean) * rstd * g1.y + c1.y;
    r[6] = (v1.z - mean) * rstd * g1.z + c1.z;
    r[7] = (v1.w - mean) * rstd * g1.w + c1.w;

    uint32_t h0, l0, h1, l1, h2, l2, h3, l3;
    split_pack(r[0], r[1], h0, l0);
    split_pack(r[2], r[3], h1, l1);
    split_pack(r[4], r[5], h2, l2);
    split_pack(r[6], r[7], h3, l3);
    size_t base = (size_t)row * D_MODEL;
    uint2 vh0 = {h0, h1}, vl0 = {l0, l1}, vh1 = {h2, h3}, vl1 = {l2, l3};
    *(uint2*)(Xh + base + tid * 4)         = vh0;
    *(uint2*)(Xh + base + (tid + 256) * 4) = vh1;
    *(uint2*)(Xl + base + tid * 4)         = vl0;
    *(uint2*)(Xl + base + (tid + 256) * 4) = vl1;
}

// ---------------- weight transpose + split (all 4 weights, grid.z selects) ----------------
__global__ __launch_bounds__(256) void transpose_split_kernel(
    const float* __restrict__ W0, const float* __restrict__ W1,
    const float* __restrict__ W2, const float* __restrict__ W3,
    __nv_bfloat16* __restrict__ Th, __nv_bfloat16* __restrict__ Tl)
{
    __shared__ float t[32][33];
    int wsel = blockIdx.z;
    const float* W = (wsel == 0) ? W0 : (wsel == 1) ? W1 : (wsel == 2) ? W2 : W3;
    size_t obase = (size_t)wsel * D_MODEL * D_MODEL;
    int bx = blockIdx.x * 32;   // n0
    int by = blockIdx.y * 32;   // k0
    int tx = threadIdx.x & 31, ty = threadIdx.x >> 5;
    #pragma unroll
    for (int r = 0; r < 4; r++)
        t[ty + r * 8][tx] = W[(size_t)(by + ty + r * 8) * D_MODEL + bx + tx];
    __syncthreads();
    #pragma unroll
    for (int r = 0; r < 4; r++) {
        float v = t[tx][ty + r * 8];
        __nv_bfloat16 h = __float2bfloat16(v);
        size_t idx = obase + (size_t)(bx + ty + r * 8) * D_MODEL + by + tx;
        Th[idx] = h;
        Tl[idx] = __float2bfloat16(v - __bfloat162float(h));
    }
}

// ---------------- HMMA bf16x3 GEMM core (single K-pass, dependency-spread MMAs) ----------------
#define TILE_B 16384
#define GDEPTH 3
#define STAGE_BYTES (4 * TILE_B)          // 64KB
#define GEMM_SMEM (GDEPTH * STAGE_BYTES)  // 192KB
#define NKITER 32

template <int SPLIT>
__device__ __forceinline__ void gemm_core(
    uint32_t sbase,
    const __nv_bfloat16* Ah, const __nv_bfloat16* Al,
    const __nv_bfloat16* Bh, const __nv_bfloat16* Bl,
    const float* bias, float* C,
    __nv_bfloat16* Ch, __nv_bfloat16* Cl,
    int bx, int by)
{
    int tid  = threadIdx.x;
    int wid  = tid >> 5;
    int lane = tid & 31;
    int wm = wid & 1;
    int wn = wid >> 1;

    float acc[4][4][4];
    #pragma unroll
    for (int i = 0; i < 4; i++)
        #pragma unroll
        for (int j = 0; j < 4; j++)
            #pragma unroll
            for (int k = 0; k < 4; k++) acc[i][j][k] = 0.f;

    int lr = lane & 7, g = lane >> 3;
    int a_row = wm * 64 + ((g & 1) << 3) + lr;
    int a_col = (g >> 1) << 4;
    int b_row = wn * 32 + ((g >> 1) << 3) + lr;
    int b_col = (g & 1) << 4;

    auto issue = [&](int it) {
        int k0 = it * 64;
        int s  = it % GDEPTH;
        uint32_t sa = sbase + s * STAGE_BYTES;
        #pragma unroll
        for (int j = 0; j < 4; j++) {
            int c = tid + j * 256;
            int r = c >> 3, c16 = c & 7;
            uint32_t off = SWZ128((uint32_t)(r * 128 + c16 * 16));
            size_t aoff = (size_t)(by + r) * D_MODEL + k0 + c16 * 8;
            size_t boff = (size_t)(bx + r) * D_MODEL + k0 + c16 * 8;
            cp_async16(sa + off,              Ah + aoff);
            cp_async16(sa + TILE_B + off,     Al + aoff);
            cp_async16(sa + 2 * TILE_B + off, Bh + boff);
            cp_async16(sa + 3 * TILE_B + off, Bl + boff);
        }
        CP_COMMIT();
    };

    issue(0); issue(1);

    for (int i = 0; i < NKITER; i++) {
        if (i + 2 < NKITER) issue(i + 2); else CP_COMMIT();
        CP_WAIT2();
        __syncthreads();

        int s = i % GDEPTH;
        uint32_t sa = sbase + s * STAGE_BYTES;

        #pragma unroll
        for (int ks = 0; ks < 4; ks++) {
            uint32_t ahf[4][4], alf[4][4], bhf[2][4], blf[2][4];
            #pragma unroll
            for (int mt = 0; mt < 4; mt++) {
                uint32_t off = SWZ128((uint32_t)((a_row + mt * 16) * 128 + ks * 32 + a_col));
                ldmx4(ahf[mt], sbase + s * STAGE_BYTES + off);
                ldmx4(alf[mt], sa + TILE_B + off);
            }
            #pragma unroll
            for (int nt = 0; nt < 2; nt++) {
                uint32_t off = SWZ128((uint32_t)((b_row + nt * 16) * 128 + ks * 32 + b_col));
                ldmx4(bhf[nt], sa + 2 * TILE_B + off);
                ldmx4(blf[nt], sa + 3 * TILE_B + off);
            }
            // three sweeps: consecutive MMAs never share an accumulator
            #pragma unroll
            for (int mt = 0; mt < 4; mt++)
                #pragma unroll
                for (int nt = 0; nt < 2; nt++) {
                    mma16816(acc[mt][nt * 2],     ahf[mt], bhf[nt]);
                    mma16816(acc[mt][nt * 2 + 1], ahf[mt], bhf[nt] + 2);
                }
            #pragma unroll
            for (int mt = 0; mt < 4; mt++)
                #pragma unroll
                for (int nt = 0; nt < 2; nt++) {
                    mma16816(acc[mt][nt * 2],     alf[mt], bhf[nt]);
                    mma16816(acc[mt][nt * 2 + 1], alf[mt], bhf[nt] + 2);
                }
            #pragma unroll
            for (int mt = 0; mt < 4; mt++)
                #pragma unroll
                for (int nt = 0; nt < 2; nt++) {
                    mma16816(acc[mt][nt * 2],     ahf[mt], blf[nt]);
                    mma16816(acc[mt][nt * 2 + 1], ahf[mt], blf[nt] + 2);
                }
        }
        __syncthreads();
    }

    int qrow = lane >> 2;
    int qcol = (lane & 3) * 2;
    #pragma unroll
    for (int mt = 0; mt < 4; mt++) {
        int m0 = by + wm * 64 + mt * 16 + qrow;
        #pragma unroll
        for (int ntt = 0; ntt < 4; ntt++) {
            int n = bx + wn * 32 + ntt * 8 + qcol;
            float2 bv = *(const float2*)&bias[n];
            float x0 = acc[mt][ntt][0] + bv.x;
            float x1 = acc[mt][ntt][1] + bv.y;
            float x2 = acc[mt][ntt][2] + bv.x;
            float x3 = acc[mt][ntt][3] + bv.y;
            if (SPLIT) {
                uint32_t h0, l0, h1, l1;
                split_pack(x0, x1, h0, l0);
                split_pack(x2, x3, h1, l1);
                *(uint32_t*)&Ch[(size_t)m0 * D_MODEL + n]       = h0;
                *(uint32_t*)&Cl[(size_t)m0 * D_MODEL + n]       = l0;
                *(uint32_t*)&Ch[(size_t)(m0 + 8) * D_MODEL + n] = h1;
                *(uint32_t*)&Cl[(size_t)(m0 + 8) * D_MODEL + n] = l1;
            } else {
                float2 r0 = {x0, x1}, r1 = {x2, x3};
                *(float2*)&C[(size_t)m0 * D_MODEL + n]       = r0;
                *(float2*)&C[(size_t)(m0 + 8) * D_MODEL + n] = r1;
            }
        }
    }
}

// fused QKV: grid.z picks the weight/bias/output triple
__global__ __launch_bounds__(256) void gemm_qkv(
    const __nv_bfloat16* __restrict__ Xh, const __nv_bfloat16* __restrict__ Xl,
    const __nv_bfloat16* __restrict__ Wth, const __nv_bfloat16* __restrict__ Wtl,
    const float* __restrict__ bq, const float* __restrict__ bk, const float* __restrict__ bv,
    __nv_bfloat16* __restrict__ Qh, __nv_bfloat16* __restrict__ Ql,
    __nv_bfloat16* __restrict__ Kh, __nv_bfloat16* __restrict__ Kl,
    __nv_bfloat16* __restrict__ Vh, __nv_bfloat16* __restrict__ Vl)
{
    extern __shared__ __align__(1024) char smc[];
    uint32_t sbase = smem_u32(smc);
    int z = blockIdx.z;
    const size_t WSZ = (size_t)D_MODEL * D_MODEL;
    const __nv_bfloat16* Bh = Wth + (size_t)z * WSZ;
    const __nv_bfloat16* Bl = Wtl + (size_t)z * WSZ;
    const float* bias = (z == 0) ? bq : (z == 1) ? bk : bv;
    __nv_bfloat16* Ch = (z == 0) ? Qh : (z == 1) ? Kh : Vh;
    __nv_bfloat16* Cl = (z == 0) ? Ql : (z == 1) ? Kl : Vl;
    gemm_core<1>(sbase, Xh, Xl, Bh, Bl, bias, nullptr, Ch, Cl,
                 blockIdx.x * 128, blockIdx.y * 128);
}

__global__ __launch_bounds__(256) void gemm_out(
    const __nv_bfloat16* __restrict__ Ah, const __nv_bfloat16* __restrict__ Al,
    const __nv_bfloat16* __restrict__ Bh, const __nv_bfloat16* __restrict__ Bl,
    const float* __restrict__ bias, float* __restrict__ C)
{
    extern __shared__ __align__(1024) char smc[];
    uint32_t sbase = smem_u32(smc);
    gemm_core<0>(sbase, Ah, Al, Bh, Bl, bias, C, nullptr, nullptr,
                 blockIdx.x * 128, blockIdx.y * 128);
}

// ---------------- HMMA flash attention (causal, bf16x3 scores + bf16x3 PV) ----------------
#define ATT_QH   0
#define ATT_QL   32768
#define ATT_STG  65536
#define ATT_STGB 65536
#define ATT_KH   0
#define ATT_KL   16384
#define ATT_VH   32768
#define ATT_VL   49152
#define ATTN_SMEM 196608
#define KSCALE 0.12751744f   // log2(e)/sqrt(128)

__global__ __launch_bounds__(256, 1) void attn_hmma(
    const __nv_bfloat16* __restrict__ Qh, const __nv_bfloat16* __restrict__ Ql,
    const __nv_bfloat16* __restrict__ Kh, const __nv_bfloat16* __restrict__ Kl,
    const __nv_bfloat16* __restrict__ Vh, const __nv_bfloat16* __restrict__ Vl,
    __nv_bfloat16* __restrict__ AVh, __nv_bfloat16* __restrict__ AVl)
{
    extern __shared__ __align__(1024) char sma[];
    uint32_t sbase = smem_u32(sma);
    int tid  = threadIdx.x;
    int wq   = tid >> 5;
    int lane = tid & 31;

    int qt = (int)gridDim.x - 1 - (int)blockIdx.x;  // long CTAs first
    int bh = blockIdx.y;
    int b  = bh >> 4, h = bh & 15;
    int q0c = qt * 128;
    int ntiles = 2 * qt + 2;

    int aq_row = wq * 16 + (lane & 15);
    int aq_csel = (lane >> 4) << 3;
    int bk_row = (lane & 7) + ((lane >> 4) << 3);
    int bk_csel = ((lane >> 3) & 1) << 3;
    int v_row = lane & 15;
    int v_csel = (lane >> 4) << 3;

    {
        #pragma unroll
        for (int j = 0; j < 8; j++) {
            int idx = tid + j * 256;
            int r = idx >> 4, c16 = idx & 15;
            uint32_t soff = (uint32_t)((c16 >> 3) * 16384 + SWZ128(r * 128 + (c16 & 7) * 16));
            size_t goff = (size_t)(b * S_LEN + q0c + r) * D_MODEL + h * D_HEAD + c16 * 8;
            cp_async16(sbase + ATT_QH + soff, Qh + goff);
            cp_async16(sbase + ATT_QL + soff, Ql + goff);
        }
        CP_COMMIT();
    }

    auto issueKV = [&](int kt) {
        int k0 = kt * 64;
        uint32_t sg = sbase + ATT_STG + (kt & 1) * ATT_STGB;
        #pragma unroll
        for (int j = 0; j < 4; j++) {
            int idx = tid + j * 256;
            int r = idx >> 4, c16 = idx & 15;
            uint32_t soff = (uint32_t)((c16 >> 3) * 8192 + SWZ128(r * 128 + (c16 & 7) * 16));
            size_t goff = (size_t)(b * S_LEN + k0 + r) * D_MODEL + h * D_HEAD + c16 * 8;
            cp_async16(sg + ATT_KH + soff, Kh + goff);
            cp_async16(sg + ATT_KL + soff, Kl + goff);
            cp_async16(sg + ATT_VH + soff, Vh + goff);
            cp_async16(sg + ATT_VL + soff, Vl + goff);
        }
        CP_COMMIT();
    };

    issueKV(0);

    float acco[16][4];
    #pragma unroll
    for (int i = 0; i < 16; i++)
        #pragma unroll
        for (int j = 0; j < 4; j++) acco[i][j] = 0.f;
    float m0 = -1e30f, m1 = -1e30f, l0 = 0.f, l1 = 0.f;

    int qcol = (lane & 3) << 1;
    int qg0 = q0c + wq * 16 + (lane >> 2);

    for (int kt = 0; kt < ntiles; kt++) {
        if (kt + 1 < ntiles) issueKV(kt + 1);
        if (kt + 1 < ntiles) { CP_WAIT1(); } else { CP_WAIT0(); }
        __syncthreads();

        uint32_t sg = sbase + ATT_STG + (kt & 1) * ATT_STGB;
        int k0 = kt * 64;

        float accs[8][4];
        #pragma unroll
        for (int i = 0; i < 8; i++)
            #pragma unroll
            for (int j = 0; j < 4; j++) accs[i][j] = 0.f;

        #pragma unroll
        for (int ks = 0; ks < 8; ks++) {
            int qc = ks * 16 + aq_csel;
            uint32_t qoff = (uint32_t)((qc >> 6) * 16384 + SWZ128(aq_row * 128 + (qc & 63) * 2));
            uint32_t aqh[4], aql[4], bk[4][4];
            ldmx4(aqh, sbase + ATT_QH + qoff);
            ldmx4(aql, sbase + ATT_QL + qoff);
            int kc = ks * 16 + bk_csel;
            uint32_t kcoff = (uint32_t)((kc >> 6) * 8192);
            #pragma unroll
            for (int ntp = 0; ntp < 4; ntp++)
                ldmx4(bk[ntp], sg + ATT_KH + kcoff + SWZ128((ntp * 16 + bk_row) * 128 + (kc & 63) * 2));
            // sweep 1: Qh*Kh over all 8 accumulators
            #pragma unroll
            for (int ntp = 0; ntp < 4; ntp++) {
                mma16816(accs[ntp * 2],     aqh, bk[ntp]);
                mma16816(accs[ntp * 2 + 1], aqh, bk[ntp] + 2);
            }
            // sweep 2: Ql*Kh
            #pragma unroll
            for (int ntp = 0; ntp < 4; ntp++) {
                mma16816(accs[ntp * 2],     aql, bk[ntp]);
                mma16816(accs[ntp * 2 + 1], aql, bk[ntp] + 2);
            }
            #pragma unroll
            for (int ntp = 0; ntp < 4; ntp++)
                ldmx4(bk[ntp], sg + ATT_KL + kcoff + SWZ128((ntp * 16 + bk_row) * 128 + (kc & 63) * 2));
            // sweep 3: Qh*Kl
            #pragma unroll
            for (int ntp = 0; ntp < 4; ntp++) {
                mma16816(accs[ntp * 2],     aqh, bk[ntp]);
                mma16816(accs[ntp * 2 + 1], aqh, bk[ntp] + 2);
            }
        }

        bool masked = (k0 + 63 > q0c);
        #pragma unroll
        for (int nt = 0; nt < 8; nt++) {
            #pragma unroll
            for (int j = 0; j < 4; j++) accs[nt][j] *= KSCALE;
            if (masked) {
                int kg = k0 + nt * 8 + qcol;
                if (kg     > qg0)     accs[nt][0] = -3e38f;
                if (kg + 1 > qg0)     accs[nt][1] = -3e38f;
                if (kg     > qg0 + 8) accs[nt][2] = -3e38f;
                if (kg + 1 > qg0 + 8) accs[nt][3] = -3e38f;
            }
        }

        float t0 = -3e38f, t1 = -3e38f;
        #pragma unroll
        for (int nt = 0; nt < 8; nt++) {
            t0 = fmaxf(t0, fmaxf(accs[nt][0], accs[nt][1]));
            t1 = fmaxf(t1, fmaxf(accs[nt][2], accs[nt][3]));
        }
        t0 = fmaxf(t0, __shfl_xor_sync(0xffffffffu, t0, 1));
        t0 = fmaxf(t0, __shfl_xor_sync(0xffffffffu, t0, 2));
        t1 = fmaxf(t1, __shfl_xor_sync(0xffffffffu, t1, 1));
        t1 = fmaxf(t1, __shfl_xor_sync(0xffffffffu, t1, 2));
        float mn0 = fmaxf(m0, t0), mn1 = fmaxf(m1, t1);
        float c0 = ex2f(m0 - mn0), c1 = ex2f(m1 - mn1);
        m0 = mn0; m1 = mn1;

        float s0 = 0.f, s1 = 0.f;
        #pragma unroll
        for (int nt = 0; nt < 8; nt++) {
            accs[nt][0] = ex2f(accs[nt][0] - mn0);
            accs[nt][1] = ex2f(accs[nt][1] - mn0);
            accs[nt][2] = ex2f(accs[nt][2] - mn1);
            accs[nt][3] = ex2f(accs[nt][3] - mn1);
            s0 += accs[nt][0] + accs[nt][1];
            s1 += accs[nt][2] + accs[nt][3];
        }
        s0 += __shfl_xor_sync(0xffffffffu, s0, 1);
        s0 += __shfl_xor_sync(0xffffffffu, s0, 2);
        s1 += __shfl_xor_sync(0xffffffffu, s1, 1);
        s1 += __shfl_xor_sync(0xffffffffu, s1, 2);
        l0 = l0 * c0 + s0;
        l1 = l1 * c1 + s1;

        #pragma unroll
        for (int nt = 0; nt < 16; nt++) {
            acco[nt][0] *= c0; acco[nt][1] *= c0;
            acco[nt][2] *= c1; acco[nt][3] *= c1;
        }

        #pragma unroll
        for (int kk = 0; kk < 4; kk++) {
            uint32_t ph[4], pl[4];
            split_pack(accs[2*kk][0],   accs[2*kk][1],   ph[0], pl[0]);
            split_pack(accs[2*kk][2],   accs[2*kk][3],   ph[1], pl[1]);
            split_pack(accs[2*kk+1][0], accs[2*kk+1][1], ph[2], pl[2]);
            split_pack(accs[2*kk+1][2], accs[2*kk+1][3], ph[3], pl[3]);
            int vr = kk * 16 + v_row;
            #pragma unroll
            for (int np = 0; np < 8; np++) {
                int n0 = np * 16 + v_csel;
                uint32_t voff = (uint32_t)((n0 >> 6) * 8192 + SWZ128(vr * 128 + (n0 & 63) * 2));
                uint32_t vf[4];
                ldmx4t(vf, sg + ATT_VH + voff);
                mma16816(acco[np * 2],     ph, vf);
                mma16816(acco[np * 2 + 1], ph, vf + 2);
                mma16816(acco[np * 2],     pl, vf);
                mma16816(acco[np * 2 + 1], pl, vf + 2);
            }
            #pragma unroll
            for (int np = 0; np < 8; np++) {
                int n0 = np * 16 + v_csel;
                uint32_t voff = (uint32_t)((n0 >> 6) * 8192 + SWZ128(vr * 128 + (n0 & 63) * 2));
                uint32_t vf[4];
                ldmx4t(vf, sg + ATT_VL + voff);
                mma16816(acco[np * 2],     ph, vf);
                mma16816(acco[np * 2 + 1], ph, vf + 2);
            }
        }
        __syncthreads();
    }

    float inv0 = 1.f / l0, inv1 = 1.f / l1;
    size_t row0 = (size_t)(b * S_LEN + qg0) * D_MODEL + h * D_HEAD;
    size_t row1 = row0 + 8 * D_MODEL;
    #pragma unroll
    for (int nt = 0; nt < 16; nt++) {
        int n = nt * 8 + qcol;
        uint32_t h0, lo0, h1, lo1;
        split_pack(acco[nt][0] * inv0, acco[nt][1] * inv0, h0, lo0);
        split_pack(acco[nt][2] * inv1, acco[nt][3] * inv1, h1, lo1);
        *(uint32_t*)&AVh[row0 + n] = h0;
        *(uint32_t*)&AVl[row0 + n] = lo0;
        *(uint32_t*)&AVh[row1 + n] = h1;
        *(uint32_t*)&AVl[row1 + n] = lo1;
    }
}

// ---------------- launch ----------------
extern "C" void kernel_launch(void* const* d_in, const int* in_sizes, int n_in,
                              void* d_out, int out_size)
{
    const float* X    = (const float*)d_in[0];
    const float* ln_g = (const float*)d_in[1];
    const float* ln_b = (const float*)d_in[2];
    const float* Wq   = (const float*)d_in[3];
    const float* bq   = (const float*)d_in[4];
    const float* Wk   = (const float*)d_in[5];
    const float* bk   = (const float*)d_in[6];
    const float* Wv   = (const float*)d_in[7];
    const float* bv   = (const float*)d_in[8];
    const float* Wo   = (const float*)d_in[9];
    const float* bo   = (const float*)d_in[10];
    float* out = (float*)d_out;

    __nv_bfloat16 *Xh, *Xl, *Qh, *Ql, *Kh, *Kl, *Vh, *Vl, *AVh, *AVl, *Wth, *Wtl;
    cudaGetSymbolAddress((void**)&Xh,  g_Xh);
    cudaGetSymbolAddress((void**)&Xl,  g_Xl);
    cudaGetSymbolAddress((void**)&Qh,  g_Qh);
    cudaGetSymbolAddress((void**)&Ql,  g_Ql);
    cudaGetSymbolAddress((void**)&Kh,  g_Kh);
    cudaGetSymbolAddress((void**)&Kl,  g_Kl);
    cudaGetSymbolAddress((void**)&Vh,  g_Vh);
    cudaGetSymbolAddress((void**)&Vl,  g_Vl);
    cudaGetSymbolAddress((void**)&AVh, g_AVh);
    cudaGetSymbolAddress((void**)&AVl, g_AVl);
    cudaGetSymbolAddress((void**)&Wth, g_Wth);
    cudaGetSymbolAddress((void**)&Wtl, g_Wtl);

    const size_t WSZ = (size_t)D_MODEL * D_MODEL;

    dim3 tg(D_MODEL / 32, D_MODEL / 32, 4);
    transpose_split_kernel<<<tg, 256>>>(Wq, Wk, Wv, Wo, Wth, Wtl);

    ln_split_kernel<<<NROWS, 256>>>(X, ln_g, ln_b, Xh, Xl);

    cudaFuncSetAttribute(gemm_qkv, cudaFuncAttributeMaxDynamicSharedMemorySize, GEMM_SMEM);
    cudaFuncSetAttribute(gemm_out, cudaFuncAttributeMaxDynamicSharedMemorySize, GEMM_SMEM);
    dim3 gq(D_MODEL / 128, NROWS / 128, 3);
    gemm_qkv<<<gq, 256, GEMM_SMEM>>>(Xh, Xl, Wth, Wtl, bq, bk, bv,
                                     Qh, Ql, Kh, Kl, Vh, Vl);

    cudaFuncSetAttribute(attn_hmma, cudaFuncAttributeMaxDynamicSharedMemorySize, ATTN_SMEM);
    attn_hmma<<<dim3(S_LEN / 128, BATCH * N_HEADS), 256, ATTN_SMEM>>>(
        Qh, Ql, Kh, Kl, Vh, Vl, AVh, AVl);

    dim3 gg(D_MODEL / 128, NROWS / 128);
    gemm_out<<<gg, 256, GEMM_SMEM>>>(AVh, AVl, Wth + 3 * WSZ, Wtl + 3 * WSZ, bo, out);
}

// round 14
// speedup vs baseline: 5.0033x; 1.0178x over previous
#include <cuda_runtime.h>
#include <cuda_bf16.h>
#include <math.h>
#include <cstdint>

#define D_MODEL 2048
#define S_LEN   2048
#define BATCH   2
#define NROWS   (BATCH * S_LEN)   // 4096
#define N_HEADS 16
#define D_HEAD  128

// ---------------- scratch (alloc-free rule: __device__ globals) ----------------
__device__ __nv_bfloat16 g_Xh [(size_t)NROWS * D_MODEL];
__device__ __nv_bfloat16 g_Xl [(size_t)NROWS * D_MODEL];
__device__ __nv_bfloat16 g_Qh [(size_t)NROWS * D_MODEL];
__device__ __nv_bfloat16 g_Ql [(size_t)NROWS * D_MODEL];
__device__ __nv_bfloat16 g_Kh [(size_t)NROWS * D_MODEL];
__device__ __nv_bfloat16 g_Kl [(size_t)NROWS * D_MODEL];
__device__ __nv_bfloat16 g_Vh [(size_t)NROWS * D_MODEL];
__device__ __nv_bfloat16 g_Vl [(size_t)NROWS * D_MODEL];
__device__ __nv_bfloat16 g_AVh[(size_t)NROWS * D_MODEL];
__device__ __nv_bfloat16 g_AVl[(size_t)NROWS * D_MODEL];
// transposed weight splits: [4][N=2048][K=2048], order: Wq, Wk, Wv, Wo
__device__ __nv_bfloat16 g_Wth[(size_t)4 * D_MODEL * D_MODEL];
__device__ __nv_bfloat16 g_Wtl[(size_t)4 * D_MODEL * D_MODEL];

// ---------------- PTX helpers (valid on plain sm_103 target) ----------------
__device__ __forceinline__ uint32_t smem_u32(const void* p) {
    uint32_t a;
    asm("{ .reg .u64 t; cvta.to.shared.u64 t, %1; cvt.u32.u64 %0, t; }" : "=r"(a) : "l"(p));
    return a;
}
#define SWZ128(off) ((off) ^ (((off) >> 3) & 0x70))
#define SWZ64(off)  ((off) ^ (((off) >> 3) & 0x30))

__device__ __forceinline__ void cp_async16(uint32_t saddr, const void* gaddr) {
    asm volatile("cp.async.cg.shared.global [%0], [%1], 16;\n" :: "r"(saddr), "l"(gaddr));
}
#define CP_COMMIT() asm volatile("cp.async.commit_group;\n" ::: "memory")
#define CP_WAIT0()  asm volatile("cp.async.wait_group 0;\n" ::: "memory")
#define CP_WAIT1()  asm volatile("cp.async.wait_group 1;\n" ::: "memory")
#define CP_WAIT2()  asm volatile("cp.async.wait_group 2;\n" ::: "memory")

__device__ __forceinline__ void ldmx4(uint32_t* r, uint32_t addr) {
    asm volatile("ldmatrix.sync.aligned.m8n8.x4.shared.b16 {%0,%1,%2,%3}, [%4];"
        : "=r"(r[0]), "=r"(r[1]), "=r"(r[2]), "=r"(r[3]) : "r"(addr));
}
__device__ __forceinline__ void ldmx4t(uint32_t* r, uint32_t addr) {
    asm volatile("ldmatrix.sync.aligned.m8n8.x4.trans.shared.b16 {%0,%1,%2,%3}, [%4];"
        : "=r"(r[0]), "=r"(r[1]), "=r"(r[2]), "=r"(r[3]) : "r"(addr));
}
// non-volatile — pure register op, lets ptxas interleave independent MMAs.
__device__ __forceinline__ void mma16816(float* d, const uint32_t* a, const uint32_t* b) {
    asm("mma.sync.aligned.m16n8k16.row.col.f32.bf16.bf16.f32 "
        "{%0,%1,%2,%3}, {%4,%5,%6,%7}, {%8,%9}, {%0,%1,%2,%3};"
        : "+f"(d[0]), "+f"(d[1]), "+f"(d[2]), "+f"(d[3])
        : "r"(a[0]), "r"(a[1]), "r"(a[2]), "r"(a[3]), "r"(b[0]), "r"(b[1]));
}
__device__ __forceinline__ float ex2f(float x) {
    float y;
    asm("ex2.approx.f32 %0, %1;" : "=f"(y) : "f"(x));
    return y;
}
__device__ __forceinline__ void split_pack(float a, float b, uint32_t& h, uint32_t& l) {
    __nv_bfloat16 ha = __float2bfloat16(a), hb = __float2bfloat16(b);
    __nv_bfloat162 th, tl;
    th.x = ha; th.y = hb;
    tl.x = __float2bfloat16(a - __bfloat162float(ha));
    tl.y = __float2bfloat16(b - __bfloat162float(hb));
    h = *(uint32_t*)&th;
    l = *(uint32_t*)&tl;
}

// ---------------- LayerNorm + bf16 split: one block per row ----------------
__global__ __launch_bounds__(256) void ln_split_kernel(
    const float* __restrict__ X, const float* __restrict__ gam,
    const float* __restrict__ bet, __nv_bfloat16* __restrict__ Xh,
    __nv_bfloat16* __restrict__ Xl)
{
    int row = blockIdx.x;
    const float4* x4 = (const float4*)(X + (size_t)row * D_MODEL);
    const float4* g4 = (const float4*)gam;
    const float4* b4 = (const float4*)bet;
    int tid = threadIdx.x;

    float4 v0 = x4[tid];
    float4 v1 = x4[tid + 256];
    float s  = v0.x + v0.y + v0.z + v0.w + v1.x + v1.y + v1.z + v1.w;
    float ss = v0.x*v0.x + v0.y*v0.y + v0.z*v0.z + v0.w*v0.w
             + v1.x*v1.x + v1.y*v1.y + v1.z*v1.z + v1.w*v1.w;

    #pragma unroll
    for (int off = 16; off; off >>= 1) {
        s  += __shfl_xor_sync(0xffffffffu, s,  off);
        ss += __shfl_xor_sync(0xffffffffu, ss, off);
    }
    __shared__ float rs[8], rss[8];
    __shared__ float s_mean, s_rstd;
    int w = tid >> 5, l = tid & 31;
    if (l == 0) { rs[w] = s; rss[w] = ss; }
    __syncthreads();
    if (tid == 0) {
        float t = 0.f, tt = 0.f;
        #pragma unroll
        for (int i = 0; i < 8; i++) { t += rs[i]; tt += rss[i]; }
        float mean = t * (1.f / D_MODEL);
        float var  = tt * (1.f / D_MODEL) - mean * mean;
        s_mean = mean;
        s_rstd = rsqrtf(var + 1e-5f);
    }
    __syncthreads();
    float mean = s_mean, rstd = s_rstd;

    float4 g0 = g4[tid], g1 = g4[tid + 256];
    float4 c0 = b4[tid], c1 = b4[tid + 256];
    float r[8];
    r[0] = (v0.x - mean) * rstd * g0.x + c0.x;
    r[1] = (v0.y - mean) * rstd * g0.y + c0.y;
    r[2] = (v0.z - mean) * rstd * g0.z + c0.z;
    r[3] = (v0.w - mean) * rstd * g0.w + c0.w;
    r[4] = (v1.x - mean) * rstd * g1.x + c1.x;
    r[5] = (v1.y - mean) * rstd * g1.y + c1.y;
    r[6] = (v1.z - mean) * rstd * g1.z + c1.z;
    r[7] = (v1.w - mean) * rstd * g1.w + c1.w;

    uint32_t h0, l0, h1, l1, h2, l2, h3, l3;
    split_pack(r[0], r[1], h0, l0);
    split_pack(r[2], r[3], h1, l1);
    split_pack(r[4], r[5], h2, l2);
    split_pack(r[6], r[7], h3, l3);
    size_t base = (size_t)row * D_MODEL;
    uint2 vh0 = {h0, h1}, vl0 = {l0, l1}, vh1 = {h2, h3}, vl1 = {l2, l3};
    *(uint2*)(Xh + base + tid * 4)         = vh0;
    *(uint2*)(Xh + base + (tid + 256) * 4) = vh1;
    *(uint2*)(Xl + base + tid * 4)         = vl0;
    *(uint2*)(Xl + base + (tid + 256) * 4) = vl1;
}

// ---------------- weight transpose + split (all 4 weights, grid.z selects) ----------------
__global__ __launch_bounds__(256) void transpose_split_kernel(
    const float* __restrict__ W0, const float* __restrict__ W1,
    const float* __restrict__ W2, const float* __restrict__ W3,
    __nv_bfloat16* __restrict__ Th, __nv_bfloat16* __restrict__ Tl)
{
    __shared__ float t[32][33];
    int wsel = blockIdx.z;
    const float* W = (wsel == 0) ? W0 : (wsel == 1) ? W1 : (wsel == 2) ? W2 : W3;
    size_t obase = (size_t)wsel * D_MODEL * D_MODEL;
    int bx = blockIdx.x * 32;   // n0
    int by = blockIdx.y * 32;   // k0
    int tx = threadIdx.x & 31, ty = threadIdx.x >> 5;
    #pragma unroll
    for (int r = 0; r < 4; r++)
        t[ty + r * 8][tx] = W[(size_t)(by + ty + r * 8) * D_MODEL + bx + tx];
    __syncthreads();
    #pragma unroll
    for (int r = 0; r < 4; r++) {
        float v = t[tx][ty + r * 8];
        __nv_bfloat16 h = __float2bfloat16(v);
        size_t idx = obase + (size_t)(bx + ty + r * 8) * D_MODEL + by + tx;
        Th[idx] = h;
        Tl[idx] = __float2bfloat16(v - __bfloat162float(h));
    }
}

// ---------------- HMMA bf16x3 GEMM core (BK=32, SW64, 2 CTAs/SM) ----------------
#define TILE_B 8192                        // 128 rows x 32 K bf16 = 8KB (64B rows)
#define GDEPTH 3
#define STAGE_BYTES (4 * TILE_B)           // 32KB: Ah|Al|Bh|Bl
#define GEMM_SMEM (GDEPTH * STAGE_BYTES)   // 96KB -> 2 CTAs/SM
#define NKITER 64                          // 2048 / 32

template <int SPLIT>
__device__ __forceinline__ void gemm_core(
    uint32_t sbase,
    const __nv_bfloat16* Ah, const __nv_bfloat16* Al,
    const __nv_bfloat16* Bh, const __nv_bfloat16* Bl,
    const float* bias, float* C,
    __nv_bfloat16* Ch, __nv_bfloat16* Cl,
    int bx, int by)
{
    int tid  = threadIdx.x;
    int wid  = tid >> 5;
    int lane = tid & 31;
    int wm = wid & 1;
    int wn = wid >> 1;

    float acc[4][4][4];
    #pragma unroll
    for (int i = 0; i < 4; i++)
        #pragma unroll
        for (int j = 0; j < 4; j++)
            #pragma unroll
            for (int k = 0; k < 4; k++) acc[i][j][k] = 0.f;

    int lr = lane & 7, g = lane >> 3;
    int a_row = wm * 64 + ((g & 1) << 3) + lr;
    int a_col = (g >> 1) << 4;
    int b_row = wn * 32 + ((g >> 1) << 3) + lr;
    int b_col = (g & 1) << 4;

    auto issue = [&](int it) {
        int k0 = it * 32;
        int s  = it % GDEPTH;
        uint32_t sa = sbase + s * STAGE_BYTES;
        #pragma unroll
        for (int j = 0; j < 2; j++) {
            int c = tid + j * 256;            // 0..511
            int r = c >> 2, c16 = c & 3;      // tile row, 16B chunk in 64B row
            uint32_t off = SWZ64((uint32_t)(r * 64 + c16 * 16));
            size_t aoff = (size_t)(by + r) * D_MODEL + k0 + c16 * 8;
            size_t boff = (size_t)(bx + r) * D_MODEL + k0 + c16 * 8;
            cp_async16(sa + off,              Ah + aoff);
            cp_async16(sa + TILE_B + off,     Al + aoff);
            cp_async16(sa + 2 * TILE_B + off, Bh + boff);
            cp_async16(sa + 3 * TILE_B + off, Bl + boff);
        }
        CP_COMMIT();
    };

    issue(0); issue(1);

    for (int i = 0; i < NKITER; i++) {
        if (i + 2 < NKITER) issue(i + 2); else CP_COMMIT();
        CP_WAIT2();
        __syncthreads();

        int s = i % GDEPTH;
        uint32_t sa = sbase + s * STAGE_BYTES;

        #pragma unroll
        for (int ks = 0; ks < 2; ks++) {
            uint32_t ahf[4][4], alf[4][4], bhf[2][4], blf[2][4];
            #pragma unroll
            for (int mt = 0; mt < 4; mt++) {
                uint32_t off = SWZ64((uint32_t)((a_row + mt * 16) * 64 + ks * 32 + a_col));
                ldmx4(ahf[mt], sa + off);
                ldmx4(alf[mt], sa + TILE_B + off);
            }
            #pragma unroll
            for (int nt = 0; nt < 2; nt++) {
                uint32_t off = SWZ64((uint32_t)((b_row + nt * 16) * 64 + ks * 32 + b_col));
                ldmx4(bhf[nt], sa + 2 * TILE_B + off);
                ldmx4(blf[nt], sa + 3 * TILE_B + off);
            }
            // three sweeps: consecutive MMAs never share an accumulator
            #pragma unroll
            for (int mt = 0; mt < 4; mt++)
                #pragma unroll
                for (int nt = 0; nt < 2; nt++) {
                    mma16816(acc[mt][nt * 2],     ahf[mt], bhf[nt]);
                    mma16816(acc[mt][nt * 2 + 1], ahf[mt], bhf[nt] + 2);
                }
            #pragma unroll
            for (int mt = 0; mt < 4; mt++)
                #pragma unroll
                for (int nt = 0; nt < 2; nt++) {
                    mma16816(acc[mt][nt * 2],     alf[mt], bhf[nt]);
                    mma16816(acc[mt][nt * 2 + 1], alf[mt], bhf[nt] + 2);
                }
            #pragma unroll
            for (int mt = 0; mt < 4; mt++)
                #pragma unroll
                for (int nt = 0; nt < 2; nt++) {
                    mma16816(acc[mt][nt * 2],     ahf[mt], blf[nt]);
                    mma16816(acc[mt][nt * 2 + 1], ahf[mt], blf[nt] + 2);
                }
        }
        __syncthreads();
    }

    int qrow = lane >> 2;
    int qcol = (lane & 3) * 2;
    #pragma unroll
    for (int mt = 0; mt < 4; mt++) {
        int m0 = by + wm * 64 + mt * 16 + qrow;
        #pragma unroll
        for (int ntt = 0; ntt < 4; ntt++) {
            int n = bx + wn * 32 + ntt * 8 + qcol;
            float2 bv = *(const float2*)&bias[n];
            float x0 = acc[mt][ntt][0] + bv.x;
            float x1 = acc[mt][ntt][1] + bv.y;
            float x2 = acc[mt][ntt][2] + bv.x;
            float x3 = acc[mt][ntt][3] + bv.y;
            if (SPLIT) {
                uint32_t h0, l0, h1, l1;
                split_pack(x0, x1, h0, l0);
                split_pack(x2, x3, h1, l1);
                *(uint32_t*)&Ch[(size_t)m0 * D_MODEL + n]       = h0;
                *(uint32_t*)&Cl[(size_t)m0 * D_MODEL + n]       = l0;
                *(uint32_t*)&Ch[(size_t)(m0 + 8) * D_MODEL + n] = h1;
                *(uint32_t*)&Cl[(size_t)(m0 + 8) * D_MODEL + n] = l1;
            } else {
                float2 r0 = {x0, x1}, r1 = {x2, x3};
                *(float2*)&C[(size_t)m0 * D_MODEL + n]       = r0;
                *(float2*)&C[(size_t)(m0 + 8) * D_MODEL + n] = r1;
            }
        }
    }
}

// fused QKV: grid.z picks the weight/bias/output triple
__global__ __launch_bounds__(256, 2) void gemm_qkv(
    const __nv_bfloat16* __restrict__ Xh, const __nv_bfloat16* __restrict__ Xl,
    const __nv_bfloat16* __restrict__ Wth, const __nv_bfloat16* __restrict__ Wtl,
    const float* __restrict__ bq, const float* __restrict__ bk, const float* __restrict__ bv,
    __nv_bfloat16* __restrict__ Qh, __nv_bfloat16* __restrict__ Ql,
    __nv_bfloat16* __restrict__ Kh, __nv_bfloat16* __restrict__ Kl,
    __nv_bfloat16* __restrict__ Vh, __nv_bfloat16* __restrict__ Vl)
{
    extern __shared__ __align__(1024) char smc[];
    uint32_t sbase = smem_u32(smc);
    int z = blockIdx.z;
    const size_t WSZ = (size_t)D_MODEL * D_MODEL;
    const __nv_bfloat16* Bh = Wth + (size_t)z * WSZ;
    const __nv_bfloat16* Bl = Wtl + (size_t)z * WSZ;
    const float* bias = (z == 0) ? bq : (z == 1) ? bk : bv;
    __nv_bfloat16* Ch = (z == 0) ? Qh : (z == 1) ? Kh : Vh;
    __nv_bfloat16* Cl = (z == 0) ? Ql : (z == 1) ? Kl : Vl;
    gemm_core<1>(sbase, Xh, Xl, Bh, Bl, bias, nullptr, Ch, Cl,
                 blockIdx.x * 128, blockIdx.y * 128);
}

__global__ __launch_bounds__(256, 2) void gemm_out(
    const __nv_bfloat16* __restrict__ Ah, const __nv_bfloat16* __restrict__ Al,
    const __nv_bfloat16* __restrict__ Bh, const __nv_bfloat16* __restrict__ Bl,
    const float* __restrict__ bias, float* __restrict__ C)
{
    extern __shared__ __align__(1024) char smc[];
    uint32_t sbase = smem_u32(smc);
    gemm_core<0>(sbase, Ah, Al, Bh, Bl, bias, C, nullptr, nullptr,
                 blockIdx.x * 128, blockIdx.y * 128);
}

// ---------------- HMMA flash attention (causal, bf16x3 scores + bf16x3 PV) ----------------
#define ATT_QH   0
#define ATT_QL   32768
#define ATT_STG  65536
#define ATT_STGB 65536
#define ATT_KH   0
#define ATT_KL   16384
#define ATT_VH   32768
#define ATT_VL   49152
#define ATTN_SMEM 196608
#define KSCALE 0.12751744f   // log2(e)/sqrt(128)

__global__ __launch_bounds__(256, 1) void attn_hmma(
    const __nv_bfloat16* __restrict__ Qh, const __nv_bfloat16* __restrict__ Ql,
    const __nv_bfloat16* __restrict__ Kh, const __nv_bfloat16* __restrict__ Kl,
    const __nv_bfloat16* __restrict__ Vh, const __nv_bfloat16* __restrict__ Vl,
    __nv_bfloat16* __restrict__ AVh, __nv_bfloat16* __restrict__ AVl)
{
    extern __shared__ __align__(1024) char sma[];
    uint32_t sbase = smem_u32(sma);
    int tid  = threadIdx.x;
    int wq   = tid >> 5;
    int lane = tid & 31;

    int qt = (int)gridDim.x - 1 - (int)blockIdx.x;  // long CTAs first
    int bh = blockIdx.y;
    int b  = bh >> 4, h = bh & 15;
    int q0c = qt * 128;
    int ntiles = 2 * qt + 2;

    int aq_row = wq * 16 + (lane & 15);
    int aq_csel = (lane >> 4) << 3;
    int bk_row = (lane & 7) + ((lane >> 4) << 3);
    int bk_csel = ((lane >> 3) & 1) << 3;
    int v_row = lane & 15;
    int v_csel = (lane >> 4) << 3;

    {
        #pragma unroll
        for (int j = 0; j < 8; j++) {
            int idx = tid + j * 256;
            int r = idx >> 4, c16 = idx & 15;
            uint32_t soff = (uint32_t)((c16 >> 3) * 16384 + SWZ128(r * 128 + (c16 & 7) * 16));
            size_t goff = (size_t)(b * S_LEN + q0c + r) * D_MODEL + h * D_HEAD + c16 * 8;
            cp_async16(sbase + ATT_QH + soff, Qh + goff);
            cp_async16(sbase + ATT_QL + soff, Ql + goff);
        }
        CP_COMMIT();
    }

    auto issueKV = [&](int kt) {
        int k0 = kt * 64;
        uint32_t sg = sbase + ATT_STG + (kt & 1) * ATT_STGB;
        #pragma unroll
        for (int j = 0; j < 4; j++) {
            int idx = tid + j * 256;
            int r = idx >> 4, c16 = idx & 15;
            uint32_t soff = (uint32_t)((c16 >> 3) * 8192 + SWZ128(r * 128 + (c16 & 7) * 16));
            size_t goff = (size_t)(b * S_LEN + k0 + r) * D_MODEL + h * D_HEAD + c16 * 8;
            cp_async16(sg + ATT_KH + soff, Kh + goff);
            cp_async16(sg + ATT_KL + soff, Kl + goff);
            cp_async16(sg + ATT_VH + soff, Vh + goff);
            cp_async16(sg + ATT_VL + soff, Vl + goff);
        }
        CP_COMMIT();
    };

    issueKV(0);

    float acco[16][4];
    #pragma unroll
    for (int i = 0; i < 16; i++)
        #pragma unroll
        for (int j = 0; j < 4; j++) acco[i][j] = 0.f;
    float m0 = -1e30f, m1 = -1e30f, l0 = 0.f, l1 = 0.f;

    int qcol = (lane & 3) << 1;
    int qg0 = q0c + wq * 16 + (lane >> 2);

    for (int kt = 0; kt < ntiles; kt++) {
        if (kt + 1 < ntiles) issueKV(kt + 1);
        if (kt + 1 < ntiles) { CP_WAIT1(); } else { CP_WAIT0(); }
        __syncthreads();

        uint32_t sg = sbase + ATT_STG + (kt & 1) * ATT_STGB;
        int k0 = kt * 64;

        float accs[8][4];
        #pragma unroll
        for (int i = 0; i < 8; i++)
            #pragma unroll
            for (int j = 0; j < 4; j++) accs[i][j] = 0.f;

        #pragma unroll
        for (int ks = 0; ks < 8; ks++) {
            int qc = ks * 16 + aq_csel;
            uint32_t qoff = (uint32_t)((qc >> 6) * 16384 + SWZ128(aq_row * 128 + (qc & 63) * 2));
            uint32_t aqh[4], aql[4], bk[4][4];
            ldmx4(aqh, sbase + ATT_QH + qoff);
            ldmx4(aql, sbase + ATT_QL + qoff);
            int kc = ks * 16 + bk_csel;
            uint32_t kcoff = (uint32_t)((kc >> 6) * 8192);
            #pragma unroll
            for (int ntp = 0; ntp < 4; ntp++)
                ldmx4(bk[ntp], sg + ATT_KH + kcoff + SWZ128((ntp * 16 + bk_row) * 128 + (kc & 63) * 2));
            #pragma unroll
            for (int ntp = 0; ntp < 4; ntp++) {
                mma16816(accs[ntp * 2],     aqh, bk[ntp]);
                mma16816(accs[ntp * 2 + 1], aqh, bk[ntp] + 2);
            }
            #pragma unroll
            for (int ntp = 0; ntp < 4; ntp++) {
                mma16816(accs[ntp * 2],     aql, bk[ntp]);
                mma16816(accs[ntp * 2 + 1], aql, bk[ntp] + 2);
            }
            #pragma unroll
            for (int ntp = 0; ntp < 4; ntp++)
                ldmx4(bk[ntp], sg + ATT_KL + kcoff + SWZ128((ntp * 16 + bk_row) * 128 + (kc & 63) * 2));
            #pragma unroll
            for (int ntp = 0; ntp < 4; ntp++) {
                mma16816(accs[ntp * 2],     aqh, bk[ntp]);
                mma16816(accs[ntp * 2 + 1], aqh, bk[ntp] + 2);
            }
        }

        bool masked = (k0 + 63 > q0c);
        #pragma unroll
        for (int nt = 0; nt < 8; nt++) {
            #pragma unroll
            for (int j = 0; j < 4; j++) accs[nt][j] *= KSCALE;
            if (masked) {
                int kg = k0 + nt * 8 + qcol;
                if (kg     > qg0)     accs[nt][0] = -3e38f;
                if (kg + 1 > qg0)     accs[nt][1] = -3e38f;
                if (kg     > qg0 + 8) accs[nt][2] = -3e38f;
                if (kg + 1 > qg0 + 8) accs[nt][3] = -3e38f;
            }
        }

        float t0 = -3e38f, t1 = -3e38f;
        #pragma unroll
        for (int nt = 0; nt < 8; nt++) {
            t0 = fmaxf(t0, fmaxf(accs[nt][0], accs[nt][1]));
            t1 = fmaxf(t1, fmaxf(accs[nt][2], accs[nt][3]));
        }
        t0 = fmaxf(t0, __shfl_xor_sync(0xffffffffu, t0, 1));
        t0 = fmaxf(t0, __shfl_xor_sync(0xffffffffu, t0, 2));
        t1 = fmaxf(t1, __shfl_xor_sync(0xffffffffu, t1, 1));
        t1 = fmaxf(t1, __shfl_xor_sync(0xffffffffu, t1, 2));
        float mn0 = fmaxf(m0, t0), mn1 = fmaxf(m1, t1);
        float c0 = ex2f(m0 - mn0), c1 = ex2f(m1 - mn1);
        m0 = mn0; m1 = mn1;

        float s0 = 0.f, s1 = 0.f;
        #pragma unroll
        for (int nt = 0; nt < 8; nt++) {
            accs[nt][0] = ex2f(accs[nt][0] - mn0);
            accs[nt][1] = ex2f(accs[nt][1] - mn0);
            accs[nt][2] = ex2f(accs[nt][2] - mn1);
            accs[nt][3] = ex2f(accs[nt][3] - mn1);
            s0 += accs[nt][0] + accs[nt][1];
            s1 += accs[nt][2] + accs[nt][3];
        }
        s0 += __shfl_xor_sync(0xffffffffu, s0, 1);
        s0 += __shfl_xor_sync(0xffffffffu, s0, 2);
        s1 += __shfl_xor_sync(0xffffffffu, s1, 1);
        s1 += __shfl_xor_sync(0xffffffffu, s1, 2);
        l0 = l0 * c0 + s0;
        l1 = l1 * c1 + s1;

        #pragma unroll
        for (int nt = 0; nt < 16; nt++) {
            acco[nt][0] *= c0; acco[nt][1] *= c0;
            acco[nt][2] *= c1; acco[nt][3] *= c1;
        }

        #pragma unroll
        for (int kk = 0; kk < 4; kk++) {
            uint32_t ph[4], pl[4];
            split_pack(accs[2*kk][0],   accs[2*kk][1],   ph[0], pl[0]);
            split_pack(accs[2*kk][2],   accs[2*kk][3],   ph[1], pl[1]);
            split_pack(accs[2*kk+1][0], accs[2*kk+1][1], ph[2], pl[2]);
            split_pack(accs[2*kk+1][2], accs[2*kk+1][3], ph[3], pl[3]);
            int vr = kk * 16 + v_row;
            #pragma unroll
            for (int np = 0; np < 8; np++) {
                int n0 = np * 16 + v_csel;
                uint32_t voff = (uint32_t)((n0 >> 6) * 8192 + SWZ128(vr * 128 + (n0 & 63) * 2));
                uint32_t vf[4];
                ldmx4t(vf, sg + ATT_VH + voff);
                mma16816(acco[np * 2],     ph, vf);
                mma16816(acco[np * 2 + 1], ph, vf + 2);
                mma16816(acco[np * 2],     pl, vf);
                mma16816(acco[np * 2 + 1], pl, vf + 2);
            }
            #pragma unroll
            for (int np = 0; np < 8; np++) {
                int n0 = np * 16 + v_csel;
                uint32_t voff = (uint32_t)((n0 >> 6) * 8192 + SWZ128(vr * 128 + (n0 & 63) * 2));
                uint32_t vf[4];
                ldmx4t(vf, sg + ATT_VL + voff);
                mma16816(acco[np * 2],     ph, vf);
                mma16816(acco[np * 2 + 1], ph, vf + 2);
            }
        }
        __syncthreads();
    }

    float inv0 = 1.f / l0, inv1 = 1.f / l1;
    size_t row0 = (size_t)(b * S_LEN + qg0) * D_MODEL + h * D_HEAD;
    size_t row1 = row0 + 8 * D_MODEL;
    #pragma unroll
    for (int nt = 0; nt < 16; nt++) {
        int n = nt * 8 + qcol;
        uint32_t h0, lo0, h1, lo1;
        split_pack(acco[nt][0] * inv0, acco[nt][1] * inv0, h0, lo0);
        split_pack(acco[nt][2] * inv1, acco[nt][3] * inv1, h1, lo1);
        *(uint32_t*)&AVh[row0 + n] = h0;
        *(uint32_t*)&AVl[row0 + n] = lo0;
        *(uint32_t*)&AVh[row1 + n] = h1;
        *(uint32_t*)&AVl[row1 + n] = lo1;
    }
}

// ---------------- launch ----------------
extern "C" void kernel_launch(void* const* d_in, const int* in_sizes, int n_in,
                              void* d_out, int out_size)
{
    const float* X    = (const float*)d_in[0];
    const float* ln_g = (const float*)d_in[1];
    const float* ln_b = (const float*)d_in[2];
    const float* Wq   = (const float*)d_in[3];
    const float* bq   = (const float*)d_in[4];
    const float* Wk   = (const float*)d_in[5];
    const float* bk   = (const float*)d_in[6];
    const float* Wv   = (const float*)d_in[7];
    const float* bv   = (const float*)d_in[8];
    const float* Wo   = (const float*)d_in[9];
    const float* bo   = (const float*)d_in[10];
    float* out = (float*)d_out;

    __nv_bfloat16 *Xh, *Xl, *Qh, *Ql, *Kh, *Kl, *Vh, *Vl, *AVh, *AVl, *Wth, *Wtl;
    cudaGetSymbolAddress((void**)&Xh,  g_Xh);
    cudaGetSymbolAddress((void**)&Xl,  g_Xl);
    cudaGetSymbolAddress((void**)&Qh,  g_Qh);
    cudaGetSymbolAddress((void**)&Ql,  g_Ql);
    cudaGetSymbolAddress((void**)&Kh,  g_Kh);
    cudaGetSymbolAddress((void**)&Kl,  g_Kl);
    cudaGetSymbolAddress((void**)&Vh,  g_Vh);
    cudaGetSymbolAddress((void**)&Vl,  g_Vl);
    cudaGetSymbolAddress((void**)&AVh, g_AVh);
    cudaGetSymbolAddress((void**)&AVl, g_AVl);
    cudaGetSymbolAddress((void**)&Wth, g_Wth);
    cudaGetSymbolAddress((void**)&Wtl, g_Wtl);

    const size_t WSZ = (size_t)D_MODEL * D_MODEL;

    dim3 tg(D_MODEL / 32, D_MODEL / 32, 4);
    transpose_split_kernel<<<tg, 256>>>(Wq, Wk, Wv, Wo, Wth, Wtl);

    ln_split_kernel<<<NROWS, 256>>>(X, ln_g, ln_b, Xh, Xl);

    cudaFuncSetAttribute(gemm_qkv, cudaFuncAttributeMaxDynamicSharedMemorySize, GEMM_SMEM);
    cudaFuncSetAttribute(gemm_out, cudaFuncAttributeMaxDynamicSharedMemorySize, GEMM_SMEM);
    dim3 gq(D_MODEL / 128, NROWS / 128, 3);
    gemm_qkv<<<gq, 256, GEMM_SMEM>>>(Xh, Xl, Wth, Wtl, bq, bk, bv,
                                     Qh, Ql, Kh, Kl, Vh, Vl);

    cudaFuncSetAttribute(attn_hmma, cudaFuncAttributeMaxDynamicSharedMemorySize, ATTN_SMEM);
    attn_hmma<<<dim3(S_LEN / 128, BATCH * N_HEADS), 256, ATTN_SMEM>>>(
        Qh, Ql, Kh, Kl, Vh, Vl, AVh, AVl);

    dim3 gg(D_MODEL / 128, NROWS / 128);
    gemm_out<<<gg, 256, GEMM_SMEM>>>(AVh, AVl, Wth + 3 * WSZ, Wtl + 3 * WSZ, bo, out);
}